// round 1
// baseline (speedup 1.0000x reference)
#include <cuda_runtime.h>
#include <cuda_bf16.h>
#include <math.h>

#define BB 2
#define TT 2048
#define DD 1024
#define HH 16
#define KNN 3
#define MM 16384
#define HDIM 64
#define NROWS (BB*TT)         // 4096
#define SCALE_F 4096.0f       // D * sqrt(H) = 1024*4

// ---------------- scratch (static device globals; no runtime allocation) ----
__device__ float g_q[NROWS * DD];
__device__ float g_k[NROWS * DD];
__device__ float g_v[NROWS * DD];
__device__ float g_attn[NROWS * DD];
__device__ float g_comb[NROWS * DD];

// ---------------------------------------------------------------------------
// C[i][j] = sum_l A[i][l] * W[j][l] + bias[j]     (A: Nx1024, W: 1024x1024)
// 128x128 tile, BK=8, 256 threads, 8x8 per thread.
// ---------------------------------------------------------------------------
__global__ __launch_bounds__(256) void sgemm_wt_bias(
    const float* __restrict__ A, const float* __restrict__ W,
    const float* __restrict__ bias, float* __restrict__ C) {
    __shared__ float As[8][132];
    __shared__ float Bs[8][132];
    const int tid = threadIdx.x;
    const int bi = blockIdx.y * 128;
    const int bj = blockIdx.x * 128;
    const int tx = tid & 15, ty = tid >> 4;
    const int lr = tid >> 1;
    const int lc = (tid & 1) * 4;

    float acc[8][8];
#pragma unroll
    for (int r = 0; r < 8; r++)
#pragma unroll
        for (int c = 0; c < 8; c++) acc[r][c] = 0.f;

    const float* Ap = A + (size_t)(bi + lr) * DD + lc;
    const float* Wp = W + (size_t)(bj + lr) * DD + lc;

    for (int l0 = 0; l0 < DD; l0 += 8) {
        float4 a4 = *(const float4*)(Ap + l0);
        float4 w4 = *(const float4*)(Wp + l0);
        __syncthreads();
        As[lc + 0][lr] = a4.x; As[lc + 1][lr] = a4.y;
        As[lc + 2][lr] = a4.z; As[lc + 3][lr] = a4.w;
        Bs[lc + 0][lr] = w4.x; Bs[lc + 1][lr] = w4.y;
        Bs[lc + 2][lr] = w4.z; Bs[lc + 3][lr] = w4.w;
        __syncthreads();
#pragma unroll
        for (int l = 0; l < 8; l++) {
            float ra[8], rb[8];
            *(float4*)(ra)     = *(const float4*)&As[l][ty * 8];
            *(float4*)(ra + 4) = *(const float4*)&As[l][ty * 8 + 4];
            *(float4*)(rb)     = *(const float4*)&Bs[l][tx * 8];
            *(float4*)(rb + 4) = *(const float4*)&Bs[l][tx * 8 + 4];
#pragma unroll
            for (int r = 0; r < 8; r++)
#pragma unroll
                for (int c = 0; c < 8; c++)
                    acc[r][c] = fmaf(ra[r], rb[c], acc[r][c]);
        }
    }

#pragma unroll
    for (int r = 0; r < 8; r++) {
        const int row = bi + ty * 8 + r;
#pragma unroll
        for (int c0 = 0; c0 < 8; c0 += 4) {
            const int col = bj + tx * 8 + c0;
            float4 o;
            o.x = acc[r][c0 + 0] + bias[col + 0];
            o.y = acc[r][c0 + 1] + bias[col + 1];
            o.z = acc[r][c0 + 2] + bias[col + 2];
            o.w = acc[r][c0 + 3] + bias[col + 3];
            *(float4*)(C + (size_t)row * DD + col) = o;
        }
    }
}

// ---------------------------------------------------------------------------
// Row L2-normalize over D=1024 (one block per row, 256 threads)
// ---------------------------------------------------------------------------
__global__ __launch_bounds__(256) void normalize_kernel(float* __restrict__ p) {
    const int row = blockIdx.x;
    const int tid = threadIdx.x;
    __shared__ float red[8];
    float4 a = *(const float4*)(p + (size_t)row * DD + tid * 4);
    float ss = a.x * a.x + a.y * a.y + a.z * a.z + a.w * a.w;
#pragma unroll
    for (int m = 16; m; m >>= 1) ss += __shfl_xor_sync(0xffffffffu, ss, m);
    if ((tid & 31) == 0) red[tid >> 5] = ss;
    __syncthreads();
    float tot = red[0] + red[1] + red[2] + red[3] +
                red[4] + red[5] + red[6] + red[7];
    float inv = 1.0f / fmaxf(sqrtf(tot), 1e-12f);
    a.x *= inv; a.y *= inv; a.z *= inv; a.w *= inv;
    *(float4*)(p + (size_t)row * DD + tid * 4) = a;
}

// ---------------------------------------------------------------------------
// Flash attention, fp32. grid = (T/64, H, B), 256 threads.
// 4 threads per query row; thread (row, quad) owns keys j = jj*4 + quad
// (interleaved so concurrent LDS.128 rows land on distinct bank phases).
// ---------------------------------------------------------------------------
#define FL_PAD 68
#define FL_SMEM (3 * 64 * FL_PAD * 4)

__global__ __launch_bounds__(256) void flash_attn_kernel(
    const float* __restrict__ q, const float* __restrict__ k,
    const float* __restrict__ v, float* __restrict__ o) {
    extern __shared__ float sm[];
    float(*Qs)[FL_PAD] = (float(*)[FL_PAD])sm;
    float(*Ks)[FL_PAD] = (float(*)[FL_PAD])(sm + 64 * FL_PAD);
    float(*Vs)[FL_PAD] = (float(*)[FL_PAD])(sm + 2 * 64 * FL_PAD);

    const int qt = blockIdx.x, h = blockIdx.y, b = blockIdx.z;
    const int tid = threadIdx.x;
    const int row = tid >> 2, quad = tid & 3;

    const float* qbase = q + (size_t)b * TT * DD + h * HDIM;
    const float* kbase = k + (size_t)b * TT * DD + h * HDIM;
    const float* vbase = v + (size_t)b * TT * DD + h * HDIM;

    // load Q tile (64 rows x 64 dims)
    {
        const float* src = qbase + (size_t)(qt * 64 + row) * DD + quad * 16;
#pragma unroll
        for (int c = 0; c < 4; c++)
            *(float4*)&Qs[row][quad * 16 + c * 4] = *(const float4*)(src + c * 4);
    }

    float O[64];
#pragma unroll
    for (int d = 0; d < 64; d++) O[d] = 0.f;
    float m_run = -1e30f, l_run = 0.f;

    for (int kt = 0; kt <= qt; kt++) {
        const float* ksrc = kbase + (size_t)(kt * 64 + row) * DD + quad * 16;
        const float* vsrc = vbase + (size_t)(kt * 64 + row) * DD + quad * 16;
        __syncthreads();
#pragma unroll
        for (int c = 0; c < 4; c++) {
            *(float4*)&Ks[row][quad * 16 + c * 4] = *(const float4*)(ksrc + c * 4);
            *(float4*)&Vs[row][quad * 16 + c * 4] = *(const float4*)(vsrc + c * 4);
        }
        __syncthreads();

        float s[16];
#pragma unroll
        for (int jj = 0; jj < 16; jj++) s[jj] = 0.f;
#pragma unroll
        for (int d4 = 0; d4 < 16; d4++) {
            float4 qv = *(const float4*)&Qs[row][d4 * 4];
#pragma unroll
            for (int jj = 0; jj < 16; jj++) {
                float4 kv = *(const float4*)&Ks[jj * 4 + quad][d4 * 4];
                s[jj] = fmaf(qv.x, kv.x, s[jj]);
                s[jj] = fmaf(qv.y, kv.y, s[jj]);
                s[jj] = fmaf(qv.z, kv.z, s[jj]);
                s[jj] = fmaf(qv.w, kv.w, s[jj]);
            }
        }
        const bool diag = (kt == qt);
#pragma unroll
        for (int jj = 0; jj < 16; jj++) {
            s[jj] *= SCALE_F;
            if (diag && ((jj << 2) + quad) > row) s[jj] = -1e30f;
        }
        float mloc = s[0];
#pragma unroll
        for (int jj = 1; jj < 16; jj++) mloc = fmaxf(mloc, s[jj]);
        mloc = fmaxf(mloc, __shfl_xor_sync(0xffffffffu, mloc, 1));
        mloc = fmaxf(mloc, __shfl_xor_sync(0xffffffffu, mloc, 2));
        const float m_new = fmaxf(m_run, mloc);
        const float alpha = __expf(m_run - m_new);
        m_run = m_new;

        float p[16];
        float psum = 0.f;
#pragma unroll
        for (int jj = 0; jj < 16; jj++) {
            p[jj] = __expf(s[jj] - m_new);
            psum += p[jj];
        }
        l_run = l_run * alpha + psum;
#pragma unroll
        for (int d = 0; d < 64; d++) O[d] *= alpha;
#pragma unroll
        for (int jj = 0; jj < 16; jj++) {
            const int j = (jj << 2) + quad;
            const float pj = p[jj];
#pragma unroll
            for (int d4 = 0; d4 < 16; d4++) {
                float4 vv = *(const float4*)&Vs[j][d4 * 4];
                O[d4 * 4 + 0] = fmaf(pj, vv.x, O[d4 * 4 + 0]);
                O[d4 * 4 + 1] = fmaf(pj, vv.y, O[d4 * 4 + 1]);
                O[d4 * 4 + 2] = fmaf(pj, vv.z, O[d4 * 4 + 2]);
                O[d4 * 4 + 3] = fmaf(pj, vv.w, O[d4 * 4 + 3]);
            }
        }
    }

    // combine the 4 partial accumulators of each row
#pragma unroll
    for (int d = 0; d < 64; d++) {
        O[d] += __shfl_xor_sync(0xffffffffu, O[d], 1);
        O[d] += __shfl_xor_sync(0xffffffffu, O[d], 2);
    }
    l_run += __shfl_xor_sync(0xffffffffu, l_run, 1);
    l_run += __shfl_xor_sync(0xffffffffu, l_run, 2);
    const float inv = 1.0f / l_run;

    float* dst = o + (size_t)(b * TT + qt * 64 + row) * DD + h * HDIM + quad * 16;
#pragma unroll
    for (int c = 0; c < 4; c++) {
        float4 w;
        w.x = O[quad * 16 + c * 4 + 0] * inv;
        w.y = O[quad * 16 + c * 4 + 1] * inv;
        w.z = O[quad * 16 + c * 4 + 2] * inv;
        w.w = O[quad * 16 + c * 4 + 3] * inv;
        *(float4*)(dst + c * 4) = w;
    }
}

// ---------------------------------------------------------------------------
// KNN memory attention + gated combine + bf16 round-trip.
// grid = B*T blocks, 256 threads: thread (h = tid/16, s = tid%16) owns 4 dims.
// ---------------------------------------------------------------------------
__global__ __launch_bounds__(256) void mem_combine_kernel(
    const float* __restrict__ q, const float* __restrict__ attn,
    const float* __restrict__ mem_bank, const int* __restrict__ knn_idx,
    const float* __restrict__ gate, float* __restrict__ comb) {
    const int bt = blockIdx.x;
    const int b = bt / TT;
    const int tid = threadIdx.x;
    const int h = tid >> 4, s16 = tid & 15;
    const int off = h * HDIM + s16 * 4;

    float4 q4 = *(const float4*)(q + (size_t)bt * DD + off);

    int idxs[KNN];
#pragma unroll
    for (int kk = 0; kk < KNN; kk++) idxs[kk] = knn_idx[bt * KNN + kk];

    float logit[KNN];
#pragma unroll
    for (int kk = 0; kk < KNN; kk++) {
        const float* mk = mem_bank + (((size_t)b * MM + idxs[kk]) * 2 + 0) * DD + off;
        float4 m4 = *(const float4*)mk;
        float d = q4.x * m4.x + q4.y * m4.y + q4.z * m4.z + q4.w * m4.w;
        d += __shfl_xor_sync(0xffffffffu, d, 1);
        d += __shfl_xor_sync(0xffffffffu, d, 2);
        d += __shfl_xor_sync(0xffffffffu, d, 4);
        d += __shfl_xor_sync(0xffffffffu, d, 8);
        logit[kk] = d * SCALE_F;
    }
    float m = fmaxf(logit[0], fmaxf(logit[1], logit[2]));
    float w0 = __expf(logit[0] - m);
    float w1 = __expf(logit[1] - m);
    float w2 = __expf(logit[2] - m);
    const float inv = 1.0f / (w0 + w1 + w2);
    w0 *= inv; w1 *= inv; w2 *= inv;
    const float wk[KNN] = {w0, w1, w2};

    float4 acc = {0.f, 0.f, 0.f, 0.f};
#pragma unroll
    for (int kk = 0; kk < KNN; kk++) {
        const float* mv = mem_bank + (((size_t)b * MM + idxs[kk]) * 2 + 1) * DD + off;
        float4 m4 = *(const float4*)mv;
        acc.x = fmaf(wk[kk], m4.x, acc.x);
        acc.y = fmaf(wk[kk], m4.y, acc.y);
        acc.z = fmaf(wk[kk], m4.z, acc.z);
        acc.w = fmaf(wk[kk], m4.w, acc.w);
    }

    const float g = gate[h];
    const float gi = 1.0f - g;
    float4 a4 = *(const float4*)(attn + (size_t)bt * DD + off);
    float4 out;
    out.x = __bfloat162float(__float2bfloat16(acc.x * g + a4.x * gi));
    out.y = __bfloat162float(__float2bfloat16(acc.y * g + a4.y * gi));
    out.z = __bfloat162float(__float2bfloat16(acc.z * g + a4.z * gi));
    out.w = __bfloat162float(__float2bfloat16(acc.w * g + a4.w * gi));
    *(float4*)(comb + (size_t)bt * DD + off) = out;
}

// ---------------------------------------------------------------------------
extern "C" void kernel_launch(void* const* d_in, const int* in_sizes, int n_in,
                              void* d_out, int out_size) {
    const float* x    = (const float*)d_in[0];
    const float* Wq   = (const float*)d_in[1];
    const float* bq   = (const float*)d_in[2];
    const float* Wk   = (const float*)d_in[3];
    const float* bk   = (const float*)d_in[4];
    const float* Wv   = (const float*)d_in[5];
    const float* bv   = (const float*)d_in[6];
    const float* Wo   = (const float*)d_in[7];
    const float* bo   = (const float*)d_in[8];
    const float* gate = (const float*)d_in[9];
    const float* memb = (const float*)d_in[10];
    const int*   knn  = (const int*)d_in[11];
    float* out = (float*)d_out;

    float *q, *k, *v, *attn, *comb;
    cudaGetSymbolAddress((void**)&q, g_q);
    cudaGetSymbolAddress((void**)&k, g_k);
    cudaGetSymbolAddress((void**)&v, g_v);
    cudaGetSymbolAddress((void**)&attn, g_attn);
    cudaGetSymbolAddress((void**)&comb, g_comb);

    cudaFuncSetAttribute(flash_attn_kernel,
                         cudaFuncAttributeMaxDynamicSharedMemorySize, FL_SMEM);

    dim3 gg(DD / 128, NROWS / 128);   // (8, 32)
    sgemm_wt_bias<<<gg, 256>>>(x, Wq, bq, q);
    sgemm_wt_bias<<<gg, 256>>>(x, Wk, bk, k);
    sgemm_wt_bias<<<gg, 256>>>(x, Wv, bv, v);

    normalize_kernel<<<NROWS, 256>>>(q);
    normalize_kernel<<<NROWS, 256>>>(k);

    flash_attn_kernel<<<dim3(TT / 64, HH, BB), 256, FL_SMEM>>>(q, k, v, attn);

    mem_combine_kernel<<<NROWS, 256>>>(q, attn, memb, knn, gate, comb);

    sgemm_wt_bias<<<gg, 256>>>(comb, Wo, bo, out);
}

// round 5
// speedup vs baseline: 1.2469x; 1.2469x over previous
#include <cuda_runtime.h>
#include <cuda_bf16.h>
#include <math.h>
#include <stdint.h>

#define BB 2
#define TT 2048
#define DD 1024
#define HH 16
#define KNN 3
#define MM 16384
#define HDIM 64
#define NROWS (BB*TT)         // 4096
#define SCALE_F 4096.0f       // D * sqrt(H)
#define K3 3072               // split-concatenated K

// ---------------- scratch (static device globals; no runtime allocation) ----
__device__ float g_q[NROWS * DD];
__device__ float g_k[NROWS * DD];
__device__ float g_v[NROWS * DD];
__device__ float g_attn[NROWS * DD];
__device__ float g_comb[NROWS * DD];
__device__ __nv_bfloat16 g_x2[NROWS * K3];   // split activations (reused for comb)
__device__ __nv_bfloat16 g_w2[DD * K3];      // split weights (reused per GEMM)

#define SWZ128(off) ((off) ^ (((off) >> 3) & 0x70))

__device__ __forceinline__ uint32_t smem_u32(const void* p) {
    uint32_t a;
    asm("{ .reg .u64 t; cvta.to.shared.u64 t, %1; cvt.u32.u64 %0, t; }"
        : "=r"(a) : "l"(p));
    return a;
}

// ---------------------------------------------------------------------------
// Split fp32 -> [hi,hi,lo] (mode 0, activations) or [hi,lo,hi] (mode 1, W)
// ---------------------------------------------------------------------------
__global__ __launch_bounds__(256) void split3_kernel(
    const float* __restrict__ X, __nv_bfloat16* __restrict__ Y, int modeB) {
    const int idx = blockIdx.x * 256 + threadIdx.x;
    const int row = idx >> 10, col = idx & 1023;
    float v = X[idx];
    __nv_bfloat16 h = __float2bfloat16(v);
    __nv_bfloat16 l = __float2bfloat16(v - __bfloat162float(h));
    __nv_bfloat16* y = Y + (size_t)row * K3 + col;
    y[0] = h;
    y[1024] = modeB ? l : h;
    y[2048] = modeB ? h : l;
}

// ---------------------------------------------------------------------------
// bf16 HMMA GEMM: C[i][j] = sum_k A2[i][k]*B2[j][k] + bias[j]
// CTA 128x128, K-chunk 64, 256 thr (8 warps, 2x4), warp tile 64x32.
// SW128-swizzled smem; ldmatrix + mma.sync m16n8k16 (baseline PTX, sm_80+).
// ---------------------------------------------------------------------------
#define GEMM_NCHUNK (K3 / 64)       // 48

__global__ __launch_bounds__(256) void gemm_mma_kernel(
    const __nv_bfloat16* __restrict__ A2, const __nv_bfloat16* __restrict__ B2,
    const float* __restrict__ bias, float* __restrict__ C) {
    __shared__ __align__(1024) char sA[128 * 128];   // 128 rows x 64 bf16
    __shared__ __align__(1024) char sB[128 * 128];

    const int tid = threadIdx.x;
    const int wid = tid >> 5, lane = tid & 31;
    const int warpM = wid >> 2, warpN = wid & 3;
    const int bi = blockIdx.y * 128, bj = blockIdx.x * 128;

    const uint32_t sa0 = smem_u32(sA);
    const uint32_t sb0 = smem_u32(sB);

    // global->smem slice: thread loads 4 A rows + 4 B rows (one uint4 each)
    const int rowL = tid >> 3;       // 0..31
    const int c16 = tid & 7;         // 16B column chunk

    float acc[4][4][4];
#pragma unroll
    for (int i = 0; i < 4; i++)
#pragma unroll
        for (int j = 0; j < 4; j++)
#pragma unroll
            for (int r = 0; r < 4; r++) acc[i][j][r] = 0.f;

    // ldmatrix lane address components (byte offsets within tile, pre-swizzle)
    const int aRow = warpM * 64 + (lane & 15);       // + i*16
    const int aHalf = (lane >> 4) * 16;
    const int bRow = warpN * 32 + (lane & 7);        // + j*8
    const int bHalf = ((lane >> 3) & 1) * 16;

    uint4 pa[4], pb[4];
#pragma unroll
    for (int i = 0; i < 4; i++) {
        pa[i] = *(const uint4*)(A2 + (size_t)(bi + rowL + i * 32) * K3 + c16 * 8);
        pb[i] = *(const uint4*)(B2 + (size_t)(bj + rowL + i * 32) * K3 + c16 * 8);
    }

    for (int c = 0; c < GEMM_NCHUNK; c++) {
        __syncthreads();
#pragma unroll
        for (int i = 0; i < 4; i++) {
            const int off = SWZ128((rowL + i * 32) * 128 + c16 * 16);
            *(uint4*)(sA + off) = pa[i];
            *(uint4*)(sB + off) = pb[i];
        }
        __syncthreads();
        if (c + 1 < GEMM_NCHUNK) {
            const int k0 = (c + 1) * 64;
#pragma unroll
            for (int i = 0; i < 4; i++) {
                pa[i] = *(const uint4*)(A2 + (size_t)(bi + rowL + i * 32) * K3 + k0 + c16 * 8);
                pb[i] = *(const uint4*)(B2 + (size_t)(bj + rowL + i * 32) * K3 + k0 + c16 * 8);
            }
        }
#pragma unroll
        for (int s = 0; s < 4; s++) {
            uint32_t af[4][4], bf[4][2];
#pragma unroll
            for (int i = 0; i < 4; i++) {
                const uint32_t ad = sa0 +
                    SWZ128((aRow + i * 16) * 128 + s * 32 + aHalf);
                asm volatile(
                    "ldmatrix.sync.aligned.m8n8.x4.shared.b16 {%0,%1,%2,%3}, [%4];"
                    : "=r"(af[i][0]), "=r"(af[i][1]), "=r"(af[i][2]), "=r"(af[i][3])
                    : "r"(ad));
            }
#pragma unroll
            for (int j = 0; j < 4; j++) {
                const uint32_t bd = sb0 +
                    SWZ128((bRow + j * 8) * 128 + s * 32 + bHalf);
                asm volatile(
                    "ldmatrix.sync.aligned.m8n8.x2.shared.b16 {%0,%1}, [%2];"
                    : "=r"(bf[j][0]), "=r"(bf[j][1])
                    : "r"(bd));
            }
#pragma unroll
            for (int i = 0; i < 4; i++)
#pragma unroll
                for (int j = 0; j < 4; j++)
                    asm volatile(
                        "mma.sync.aligned.m16n8k16.row.col.f32.bf16.bf16.f32 "
                        "{%0,%1,%2,%3}, {%4,%5,%6,%7}, {%8,%9}, {%0,%1,%2,%3};"
                        : "+f"(acc[i][j][0]), "+f"(acc[i][j][1]),
                          "+f"(acc[i][j][2]), "+f"(acc[i][j][3])
                        : "r"(af[i][0]), "r"(af[i][1]), "r"(af[i][2]), "r"(af[i][3]),
                          "r"(bf[j][0]), "r"(bf[j][1]));
        }
    }

    // epilogue: d0,d1 -> row m0+lane/4, cols +0,+1; d2,d3 -> row +8
#pragma unroll
    for (int i = 0; i < 4; i++) {
        const int r0 = bi + warpM * 64 + i * 16 + (lane >> 2);
#pragma unroll
        for (int j = 0; j < 4; j++) {
            const int c0 = bj + warpN * 32 + j * 8 + (lane & 3) * 2;
            const float b0 = bias[c0], b1 = bias[c0 + 1];
            float2 o0 = make_float2(acc[i][j][0] + b0, acc[i][j][1] + b1);
            float2 o1 = make_float2(acc[i][j][2] + b0, acc[i][j][3] + b1);
            *(float2*)(C + (size_t)r0 * DD + c0) = o0;
            *(float2*)(C + (size_t)(r0 + 8) * DD + c0) = o1;
        }
    }
}

// ---------------------------------------------------------------------------
// Row L2-normalize over D=1024 (one block per row, 256 threads)
// ---------------------------------------------------------------------------
__global__ __launch_bounds__(256) void normalize_kernel(float* __restrict__ p) {
    const int row = blockIdx.x;
    const int tid = threadIdx.x;
    __shared__ float red[8];
    float4 a = *(const float4*)(p + (size_t)row * DD + tid * 4);
    float ss = a.x * a.x + a.y * a.y + a.z * a.z + a.w * a.w;
#pragma unroll
    for (int m = 16; m; m >>= 1) ss += __shfl_xor_sync(0xffffffffu, ss, m);
    if ((tid & 31) == 0) red[tid >> 5] = ss;
    __syncthreads();
    float tot = red[0] + red[1] + red[2] + red[3] +
                red[4] + red[5] + red[6] + red[7];
    float inv = 1.0f / fmaxf(sqrtf(tot), 1e-12f);
    a.x *= inv; a.y *= inv; a.z *= inv; a.w *= inv;
    *(float4*)(p + (size_t)row * DD + tid * 4) = a;
}

// ---------------------------------------------------------------------------
// Flash attention, fp32. grid = (T/64, H, B), 256 threads.
// ---------------------------------------------------------------------------
#define FL_PAD 68
#define FL_SMEM (3 * 64 * FL_PAD * 4)

__global__ __launch_bounds__(256) void flash_attn_kernel(
    const float* __restrict__ q, const float* __restrict__ k,
    const float* __restrict__ v, float* __restrict__ o) {
    extern __shared__ float sm[];
    float(*Qs)[FL_PAD] = (float(*)[FL_PAD])sm;
    float(*Ks)[FL_PAD] = (float(*)[FL_PAD])(sm + 64 * FL_PAD);
    float(*Vs)[FL_PAD] = (float(*)[FL_PAD])(sm + 2 * 64 * FL_PAD);

    const int qt = blockIdx.x, h = blockIdx.y, b = blockIdx.z;
    const int tid = threadIdx.x;
    const int row = tid >> 2, quad = tid & 3;

    const float* qbase = q + (size_t)b * TT * DD + h * HDIM;
    const float* kbase = k + (size_t)b * TT * DD + h * HDIM;
    const float* vbase = v + (size_t)b * TT * DD + h * HDIM;

    {
        const float* src = qbase + (size_t)(qt * 64 + row) * DD + quad * 16;
#pragma unroll
        for (int c = 0; c < 4; c++)
            *(float4*)&Qs[row][quad * 16 + c * 4] = *(const float4*)(src + c * 4);
    }

    float O[64];
#pragma unroll
    for (int d = 0; d < 64; d++) O[d] = 0.f;
    float m_run = -1e30f, l_run = 0.f;

    for (int kt = 0; kt <= qt; kt++) {
        const float* ksrc = kbase + (size_t)(kt * 64 + row) * DD + quad * 16;
        const float* vsrc = vbase + (size_t)(kt * 64 + row) * DD + quad * 16;
        __syncthreads();
#pragma unroll
        for (int c = 0; c < 4; c++) {
            *(float4*)&Ks[row][quad * 16 + c * 4] = *(const float4*)(ksrc + c * 4);
            *(float4*)&Vs[row][quad * 16 + c * 4] = *(const float4*)(vsrc + c * 4);
        }
        __syncthreads();

        float s[16];
#pragma unroll
        for (int jj = 0; jj < 16; jj++) s[jj] = 0.f;
#pragma unroll
        for (int d4 = 0; d4 < 16; d4++) {
            float4 qv = *(const float4*)&Qs[row][d4 * 4];
#pragma unroll
            for (int jj = 0; jj < 16; jj++) {
                float4 kv = *(const float4*)&Ks[jj * 4 + quad][d4 * 4];
                s[jj] = fmaf(qv.x, kv.x, s[jj]);
                s[jj] = fmaf(qv.y, kv.y, s[jj]);
                s[jj] = fmaf(qv.z, kv.z, s[jj]);
                s[jj] = fmaf(qv.w, kv.w, s[jj]);
            }
        }
        const bool diag = (kt == qt);
#pragma unroll
        for (int jj = 0; jj < 16; jj++) {
            s[jj] *= SCALE_F;
            if (diag && ((jj << 2) + quad) > row) s[jj] = -1e30f;
        }
        float mloc = s[0];
#pragma unroll
        for (int jj = 1; jj < 16; jj++) mloc = fmaxf(mloc, s[jj]);
        mloc = fmaxf(mloc, __shfl_xor_sync(0xffffffffu, mloc, 1));
        mloc = fmaxf(mloc, __shfl_xor_sync(0xffffffffu, mloc, 2));
        const float m_new = fmaxf(m_run, mloc);
        const float alpha = __expf(m_run - m_new);
        m_run = m_new;

        float p[16];
        float psum = 0.f;
#pragma unroll
        for (int jj = 0; jj < 16; jj++) {
            p[jj] = __expf(s[jj] - m_new);
            psum += p[jj];
        }
        l_run = l_run * alpha + psum;
#pragma unroll
        for (int d = 0; d < 64; d++) O[d] *= alpha;
#pragma unroll
        for (int jj = 0; jj < 16; jj++) {
            const int j = (jj << 2) + quad;
            const float pj = p[jj];
#pragma unroll
            for (int d4 = 0; d4 < 16; d4++) {
                float4 vv = *(const float4*)&Vs[j][d4 * 4];
                O[d4 * 4 + 0] = fmaf(pj, vv.x, O[d4 * 4 + 0]);
                O[d4 * 4 + 1] = fmaf(pj, vv.y, O[d4 * 4 + 1]);
                O[d4 * 4 + 2] = fmaf(pj, vv.z, O[d4 * 4 + 2]);
                O[d4 * 4 + 3] = fmaf(pj, vv.w, O[d4 * 4 + 3]);
            }
        }
    }

#pragma unroll
    for (int d = 0; d < 64; d++) {
        O[d] += __shfl_xor_sync(0xffffffffu, O[d], 1);
        O[d] += __shfl_xor_sync(0xffffffffu, O[d], 2);
    }
    l_run += __shfl_xor_sync(0xffffffffu, l_run, 1);
    l_run += __shfl_xor_sync(0xffffffffu, l_run, 2);
    const float inv = 1.0f / l_run;

    float* dst = o + (size_t)(b * TT + qt * 64 + row) * DD + h * HDIM + quad * 16;
#pragma unroll
    for (int c = 0; c < 4; c++) {
        float4 w;
        w.x = O[quad * 16 + c * 4 + 0] * inv;
        w.y = O[quad * 16 + c * 4 + 1] * inv;
        w.z = O[quad * 16 + c * 4 + 2] * inv;
        w.w = O[quad * 16 + c * 4 + 3] * inv;
        *(float4*)(dst + c * 4) = w;
    }
}

// ---------------------------------------------------------------------------
// KNN memory attention + gated combine + bf16 round-trip.
// ---------------------------------------------------------------------------
__global__ __launch_bounds__(256) void mem_combine_kernel(
    const float* __restrict__ q, const float* __restrict__ attn,
    const float* __restrict__ mem_bank, const int* __restrict__ knn_idx,
    const float* __restrict__ gate, float* __restrict__ comb) {
    const int bt = blockIdx.x;
    const int b = bt / TT;
    const int tid = threadIdx.x;
    const int h = tid >> 4, s16 = tid & 15;
    const int off = h * HDIM + s16 * 4;

    float4 q4 = *(const float4*)(q + (size_t)bt * DD + off);

    int idxs[KNN];
#pragma unroll
    for (int kk = 0; kk < KNN; kk++) idxs[kk] = knn_idx[bt * KNN + kk];

    float logit[KNN];
#pragma unroll
    for (int kk = 0; kk < KNN; kk++) {
        const float* mk = mem_bank + (((size_t)b * MM + idxs[kk]) * 2 + 0) * DD + off;
        float4 m4 = *(const float4*)mk;
        float d = q4.x * m4.x + q4.y * m4.y + q4.z * m4.z + q4.w * m4.w;
        d += __shfl_xor_sync(0xffffffffu, d, 1);
        d += __shfl_xor_sync(0xffffffffu, d, 2);
        d += __shfl_xor_sync(0xffffffffu, d, 4);
        d += __shfl_xor_sync(0xffffffffu, d, 8);
        logit[kk] = d * SCALE_F;
    }
    float m = fmaxf(logit[0], fmaxf(logit[1], logit[2]));
    float w0 = __expf(logit[0] - m);
    float w1 = __expf(logit[1] - m);
    float w2 = __expf(logit[2] - m);
    const float inv = 1.0f / (w0 + w1 + w2);
    w0 *= inv; w1 *= inv; w2 *= inv;
    const float wk[KNN] = {w0, w1, w2};

    float4 acc = {0.f, 0.f, 0.f, 0.f};
#pragma unroll
    for (int kk = 0; kk < KNN; kk++) {
        const float* mv = mem_bank + (((size_t)b * MM + idxs[kk]) * 2 + 1) * DD + off;
        float4 m4 = *(const float4*)mv;
        acc.x = fmaf(wk[kk], m4.x, acc.x);
        acc.y = fmaf(wk[kk], m4.y, acc.y);
        acc.z = fmaf(wk[kk], m4.z, acc.z);
        acc.w = fmaf(wk[kk], m4.w, acc.w);
    }

    const float g = gate[h];
    const float gi = 1.0f - g;
    float4 a4 = *(const float4*)(attn + (size_t)bt * DD + off);
    float4 out;
    out.x = __bfloat162float(__float2bfloat16(acc.x * g + a4.x * gi));
    out.y = __bfloat162float(__float2bfloat16(acc.y * g + a4.y * gi));
    out.z = __bfloat162float(__float2bfloat16(acc.z * g + a4.z * gi));
    out.w = __bfloat162float(__float2bfloat16(acc.w * g + a4.w * gi));
    *(float4*)(comb + (size_t)bt * DD + off) = out;
}

// ---------------------------------------------------------------------------
extern "C" void kernel_launch(void* const* d_in, const int* in_sizes, int n_in,
                              void* d_out, int out_size) {
    const float* x    = (const float*)d_in[0];
    const float* Wq   = (const float*)d_in[1];
    const float* bq   = (const float*)d_in[2];
    const float* Wk   = (const float*)d_in[3];
    const float* bk   = (const float*)d_in[4];
    const float* Wv   = (const float*)d_in[5];
    const float* bv   = (const float*)d_in[6];
    const float* Wo   = (const float*)d_in[7];
    const float* bo   = (const float*)d_in[8];
    const float* gate = (const float*)d_in[9];
    const float* memb = (const float*)d_in[10];
    const int*   knn  = (const int*)d_in[11];
    float* out = (float*)d_out;

    float *q, *k, *v, *attn, *comb;
    __nv_bfloat16 *x2, *w2;
    cudaGetSymbolAddress((void**)&q, g_q);
    cudaGetSymbolAddress((void**)&k, g_k);
    cudaGetSymbolAddress((void**)&v, g_v);
    cudaGetSymbolAddress((void**)&attn, g_attn);
    cudaGetSymbolAddress((void**)&comb, g_comb);
    cudaGetSymbolAddress((void**)&x2, g_x2);
    cudaGetSymbolAddress((void**)&w2, g_w2);

    cudaFuncSetAttribute(flash_attn_kernel,
                         cudaFuncAttributeMaxDynamicSharedMemorySize, FL_SMEM);

    const dim3 gg(DD / 128, NROWS / 128);   // (8, 32)

    // split activations once; weights split sequentially into shared buffer
    split3_kernel<<<NROWS * DD / 256, 256>>>(x, x2, 0);

    split3_kernel<<<DD * DD / 256, 256>>>(Wq, w2, 1);
    gemm_mma_kernel<<<gg, 256>>>(x2, w2, bq, q);
    split3_kernel<<<DD * DD / 256, 256>>>(Wk, w2, 1);
    gemm_mma_kernel<<<gg, 256>>>(x2, w2, bk, k);
    split3_kernel<<<DD * DD / 256, 256>>>(Wv, w2, 1);
    gemm_mma_kernel<<<gg, 256>>>(x2, w2, bv, v);

    normalize_kernel<<<NROWS, 256>>>(q);
    normalize_kernel<<<NROWS, 256>>>(k);

    flash_attn_kernel<<<dim3(TT / 64, HH, BB), 256, FL_SMEM>>>(q, k, v, attn);

    mem_combine_kernel<<<NROWS, 256>>>(q, attn, memb, knn, gate, comb);

    // reuse x2 for combined activations
    split3_kernel<<<NROWS * DD / 256, 256>>>(comb, x2, 0);
    split3_kernel<<<DD * DD / 256, 256>>>(Wo, w2, 1);
    gemm_mma_kernel<<<gg, 256>>>(x2, w2, bo, out);
}

// round 7
// speedup vs baseline: 3.1477x; 2.5244x over previous
#include <cuda_runtime.h>
#include <cuda_bf16.h>
#include <math.h>
#include <stdint.h>

#define BB 2
#define TT 2048
#define DD 1024
#define HH 16
#define KNN 3
#define MM 16384
#define HDIM 64
#define NROWS (BB*TT)         // 4096
#define SCALE_F 4096.0f       // D * sqrt(H)
#define K3 3072               // split-concatenated K
#define PLANE (NROWS * DD)    // 4M elems: hi plane size; lo at +PLANE

// ---------------- scratch (static device globals; no runtime allocation) ----
__device__ float g_q[NROWS * DD];
__device__ float g_k[NROWS * DD];
__device__ float g_v[NROWS * DD];
__device__ float g_attn[NROWS * DD];
__device__ float g_comb[NROWS * DD];
__device__ __nv_bfloat16 g_x2[NROWS * K3];   // split activations (reused for comb)
__device__ __nv_bfloat16 g_w2[DD * K3];      // split weights (reused per GEMM)
__device__ __nv_bfloat16 g_qs[2 * PLANE];    // per-head (b,h,t,64) hi/lo
__device__ __nv_bfloat16 g_ks[2 * PLANE];
__device__ __nv_bfloat16 g_vs[2 * PLANE];

#define SWZ128(off) ((off) ^ (((off) >> 3) & 0x70))

__device__ __forceinline__ uint32_t smem_u32(const void* p) {
    uint32_t a;
    asm("{ .reg .u64 t; cvta.to.shared.u64 t, %1; cvt.u32.u64 %0, t; }"
        : "=r"(a) : "l"(p));
    return a;
}
__device__ __forceinline__ void ldm_x4(uint32_t* r, uint32_t addr) {
    asm volatile("ldmatrix.sync.aligned.m8n8.x4.shared.b16 {%0,%1,%2,%3}, [%4];"
                 : "=r"(r[0]), "=r"(r[1]), "=r"(r[2]), "=r"(r[3]) : "r"(addr));
}
__device__ __forceinline__ void ldm_x2(uint32_t* r, uint32_t addr) {
    asm volatile("ldmatrix.sync.aligned.m8n8.x2.shared.b16 {%0,%1}, [%2];"
                 : "=r"(r[0]), "=r"(r[1]) : "r"(addr));
}
__device__ __forceinline__ void ldm_x2t(uint32_t* r, uint32_t addr) {
    asm volatile("ldmatrix.sync.aligned.m8n8.x2.trans.shared.b16 {%0,%1}, [%2];"
                 : "=r"(r[0]), "=r"(r[1]) : "r"(addr));
}
__device__ __forceinline__ void mma16816(float* d, const uint32_t* a, const uint32_t* b) {
    asm volatile(
        "mma.sync.aligned.m16n8k16.row.col.f32.bf16.bf16.f32 "
        "{%0,%1,%2,%3}, {%4,%5,%6,%7}, {%8,%9}, {%0,%1,%2,%3};"
        : "+f"(d[0]), "+f"(d[1]), "+f"(d[2]), "+f"(d[3])
        : "r"(a[0]), "r"(a[1]), "r"(a[2]), "r"(a[3]), "r"(b[0]), "r"(b[1]));
}
__device__ __forceinline__ uint32_t packbf2(float lo, float hi) {
    uint32_t r;
    asm("cvt.rn.bf16x2.f32 %0, %1, %2;" : "=r"(r) : "f"(hi), "f"(lo));
    return r;
}

// ---------------------------------------------------------------------------
// Split fp32 -> [hi,hi,lo] (mode 0, activations) or [hi,lo,hi] (mode 1, W)
// ---------------------------------------------------------------------------
__global__ __launch_bounds__(256) void split3_kernel(
    const float* __restrict__ X, __nv_bfloat16* __restrict__ Y, int modeB) {
    const int idx = blockIdx.x * 256 + threadIdx.x;
    const int row = idx >> 10, col = idx & 1023;
    float v = X[idx];
    __nv_bfloat16 h = __float2bfloat16(v);
    __nv_bfloat16 l = __float2bfloat16(v - __bfloat162float(h));
    __nv_bfloat16* y = Y + (size_t)row * K3 + col;
    y[0] = h;
    y[1024] = modeB ? l : h;
    y[2048] = modeB ? h : l;
}

// ---------------------------------------------------------------------------
// bf16 HMMA GEMM: C[i][j] = sum_k A2[i][k]*B2[j][k] + bias[j]
// ---------------------------------------------------------------------------
#define GEMM_NCHUNK (K3 / 64)       // 48

__global__ __launch_bounds__(256) void gemm_mma_kernel(
    const __nv_bfloat16* __restrict__ A2, const __nv_bfloat16* __restrict__ B2,
    const float* __restrict__ bias, float* __restrict__ C) {
    __shared__ __align__(1024) char sA[128 * 128];
    __shared__ __align__(1024) char sB[128 * 128];

    const int tid = threadIdx.x;
    const int wid = tid >> 5, lane = tid & 31;
    const int warpM = wid >> 2, warpN = wid & 3;
    const int bi = blockIdx.y * 128, bj = blockIdx.x * 128;

    const uint32_t sa0 = smem_u32(sA);
    const uint32_t sb0 = smem_u32(sB);

    const int rowL = tid >> 3;
    const int c16 = tid & 7;

    float acc[4][4][4];
#pragma unroll
    for (int i = 0; i < 4; i++)
#pragma unroll
        for (int j = 0; j < 4; j++)
#pragma unroll
            for (int r = 0; r < 4; r++) acc[i][j][r] = 0.f;

    const int aRow = warpM * 64 + (lane & 15);
    const int aHalf = (lane >> 4) * 16;
    const int bRow = warpN * 32 + (lane & 7);
    const int bHalf = ((lane >> 3) & 1) * 16;

    uint4 pa[4], pb[4];
#pragma unroll
    for (int i = 0; i < 4; i++) {
        pa[i] = *(const uint4*)(A2 + (size_t)(bi + rowL + i * 32) * K3 + c16 * 8);
        pb[i] = *(const uint4*)(B2 + (size_t)(bj + rowL + i * 32) * K3 + c16 * 8);
    }

    for (int c = 0; c < GEMM_NCHUNK; c++) {
        __syncthreads();
#pragma unroll
        for (int i = 0; i < 4; i++) {
            const int off = SWZ128((rowL + i * 32) * 128 + c16 * 16);
            *(uint4*)(sA + off) = pa[i];
            *(uint4*)(sB + off) = pb[i];
        }
        __syncthreads();
        if (c + 1 < GEMM_NCHUNK) {
            const int k0 = (c + 1) * 64;
#pragma unroll
            for (int i = 0; i < 4; i++) {
                pa[i] = *(const uint4*)(A2 + (size_t)(bi + rowL + i * 32) * K3 + k0 + c16 * 8);
                pb[i] = *(const uint4*)(B2 + (size_t)(bj + rowL + i * 32) * K3 + k0 + c16 * 8);
            }
        }
#pragma unroll
        for (int s = 0; s < 4; s++) {
            uint32_t af[4][4], bf[4][2];
#pragma unroll
            for (int i = 0; i < 4; i++)
                ldm_x4(af[i], sa0 + SWZ128((aRow + i * 16) * 128 + s * 32 + aHalf));
#pragma unroll
            for (int j = 0; j < 4; j++)
                ldm_x2(bf[j], sb0 + SWZ128((bRow + j * 8) * 128 + s * 32 + bHalf));
#pragma unroll
            for (int i = 0; i < 4; i++)
#pragma unroll
                for (int j = 0; j < 4; j++)
                    mma16816(acc[i][j], af[i], bf[j]);
        }
    }

#pragma unroll
    for (int i = 0; i < 4; i++) {
        const int r0 = bi + warpM * 64 + i * 16 + (lane >> 2);
#pragma unroll
        for (int j = 0; j < 4; j++) {
            const int c0 = bj + warpN * 32 + j * 8 + (lane & 3) * 2;
            const float b0 = bias[c0], b1 = bias[c0 + 1];
            float2 o0 = make_float2(acc[i][j][0] + b0, acc[i][j][1] + b1);
            float2 o1 = make_float2(acc[i][j][2] + b0, acc[i][j][3] + b1);
            *(float2*)(C + (size_t)r0 * DD + c0) = o0;
            *(float2*)(C + (size_t)(r0 + 8) * DD + c0) = o1;
        }
    }
}

// ---------------------------------------------------------------------------
// Optional row L2-normalize + hi/lo bf16 split into per-head (b,h,t,64) planes.
// One block per (b,t) row, 256 threads (4 elems each).
// ---------------------------------------------------------------------------
__global__ __launch_bounds__(256) void norm_split_kernel(
    float* __restrict__ p, __nv_bfloat16* __restrict__ Y,
    int do_norm, int writeback) {
    const int row = blockIdx.x;
    const int b = row >> 11, t = row & 2047;
    const int tid = threadIdx.x;
    __shared__ float red[8];
    float4 a = *(const float4*)(p + (size_t)row * DD + tid * 4);
    if (do_norm) {
        float ss = a.x * a.x + a.y * a.y + a.z * a.z + a.w * a.w;
#pragma unroll
        for (int m = 16; m; m >>= 1) ss += __shfl_xor_sync(0xffffffffu, ss, m);
        if ((tid & 31) == 0) red[tid >> 5] = ss;
        __syncthreads();
        float tot = red[0] + red[1] + red[2] + red[3] +
                    red[4] + red[5] + red[6] + red[7];
        float inv = 1.0f / fmaxf(sqrtf(tot), 1e-12f);
        a.x *= inv; a.y *= inv; a.z *= inv; a.w *= inv;
        if (writeback)
            *(float4*)(p + (size_t)row * DD + tid * 4) = a;
    }
    const int h = tid >> 4;
    const int dh = (tid & 15) * 4;
    __nv_bfloat16* dst = Y + ((size_t)(b * HH + h) * TT + t) * 64 + dh;
    __nv_bfloat16 hi[4], lo[4];
    const float* av = (const float*)&a;
#pragma unroll
    for (int i = 0; i < 4; i++) {
        hi[i] = __float2bfloat16(av[i]);
        lo[i] = __float2bfloat16(av[i] - __bfloat162float(hi[i]));
    }
    *(uint2*)dst = *(const uint2*)hi;
    *(uint2*)(dst + PLANE) = *(const uint2*)lo;
}

// ---------------------------------------------------------------------------
// Flash attention via bf16 mma with hi/lo 3-term splits.
// grid (16, H, B): qt = 15 - blockIdx.x (long blocks first), 128 q-rows/block,
// 256 threads (8 warps x 16 rows), 64-key tiles.
// ---------------------------------------------------------------------------
#define FLM_SMEM 65536

__global__ __launch_bounds__(256) void flash_mma_kernel(
    const __nv_bfloat16* __restrict__ qs, const __nv_bfloat16* __restrict__ ks,
    const __nv_bfloat16* __restrict__ vs, float* __restrict__ attn) {
    extern __shared__ char sm[];
    const uint32_t sQh = smem_u32(sm);
    const uint32_t sQl = sQh + 16384;
    const uint32_t sKh = sQh + 32768;
    const uint32_t sKl = sQh + 40960;
    const uint32_t sVh = sQh + 49152;
    const uint32_t sVl = sQh + 57344;

    const int qt = 15 - blockIdx.x;
    const int h = blockIdx.y, b = blockIdx.z;
    const int tid = threadIdx.x, wid = tid >> 5, lane = tid & 31;
    const size_t hb = ((size_t)(b * HH + h)) * TT * 64;

    // load Q tile: 128 rows x 64 bf16 (hi+lo)
    {
        const int row = tid >> 1, part = tid & 1;
        const __nv_bfloat16* srcH = qs + hb + (size_t)(qt * 128 + row) * 64 + part * 32;
        const __nv_bfloat16* srcL = srcH + PLANE;
#pragma unroll
        for (int i = 0; i < 4; i++) {
            const int off = SWZ128(row * 128 + part * 64 + i * 16);
            *(uint4*)(sm + (sQh - sQh) + off) = *(const uint4*)(srcH + i * 8);
            *(uint4*)(sm + 16384 + off) = *(const uint4*)(srcL + i * 8);
        }
    }

    float out[8][4];
#pragma unroll
    for (int nt = 0; nt < 8; nt++)
#pragma unroll
        for (int r = 0; r < 4; r++) out[nt][r] = 0.f;
    float m0 = -1e30f, m1 = -1e30f, l0 = 0.f, l1 = 0.f;

    const int r4 = lane >> 2;
    const int cpair = (lane & 3) * 2;
    const int rowg0 = qt * 128 + wid * 16 + r4;
    const int rowg1 = rowg0 + 8;
    const int rowmax = qt * 128 + wid * 16 + 15;
    const int warpmin = qt * 128 + wid * 16;

    // ldmatrix address components
    const int qRow = wid * 16 + (lane & 15);
    const int qHalf = (lane >> 4) * 16;
    const int kRowL = lane & 7;
    const int kHalf = ((lane >> 3) & 1) * 16;
    const int vRowL = (lane & 7) + ((lane >> 3) & 1) * 8;

    const int ktmax = 2 * qt + 1;
    for (int kt = 0; kt <= ktmax; kt++) {
        const int j0 = kt * 64;
        __syncthreads();
        {   // load K/V tiles (hi+lo): 64 rows x 64 bf16 each
            const int row = tid >> 2, c = tid & 3;
            const size_t src = hb + (size_t)(j0 + row) * 64 + c * 16;
            const int d0 = SWZ128(row * 128 + c * 32);
            const int d1 = SWZ128(row * 128 + c * 32 + 16);
            *(uint4*)(sm + 32768 + d0) = *(const uint4*)(ks + src);
            *(uint4*)(sm + 32768 + d1) = *(const uint4*)(ks + src + 8);
            *(uint4*)(sm + 40960 + d0) = *(const uint4*)(ks + PLANE + src);
            *(uint4*)(sm + 40960 + d1) = *(const uint4*)(ks + PLANE + src + 8);
            *(uint4*)(sm + 49152 + d0) = *(const uint4*)(vs + src);
            *(uint4*)(sm + 49152 + d1) = *(const uint4*)(vs + src + 8);
            *(uint4*)(sm + 57344 + d0) = *(const uint4*)(vs + PLANE + src);
            *(uint4*)(sm + 57344 + d1) = *(const uint4*)(vs + PLANE + src + 8);
        }
        __syncthreads();
        if (j0 > rowmax) continue;   // no syncs below: safe divergence

        // ---- S = Q K^T (3-term split), fp32 accum ----
        float s[8][4];
#pragma unroll
        for (int nt = 0; nt < 8; nt++)
#pragma unroll
            for (int r = 0; r < 4; r++) s[nt][r] = 0.f;
#pragma unroll
        for (int s4 = 0; s4 < 4; s4++) {
            uint32_t ah[4], al[4];
            ldm_x4(ah, sQh + SWZ128(qRow * 128 + s4 * 32 + qHalf));
            ldm_x4(al, sQl + SWZ128(qRow * 128 + s4 * 32 + qHalf));
#pragma unroll
            for (int nt = 0; nt < 8; nt++) {
                uint32_t bh[2], bl[2];
                const int boff = SWZ128((nt * 8 + kRowL) * 128 + s4 * 32 + kHalf);
                ldm_x2(bh, sKh + boff);
                ldm_x2(bl, sKl + boff);
                mma16816(s[nt], ah, bh);
                mma16816(s[nt], al, bh);
                mma16816(s[nt], ah, bl);
            }
        }

        // ---- scale + causal mask ----
        if (j0 + 63 > warpmin) {
#pragma unroll
            for (int nt = 0; nt < 8; nt++) {
                const int c0 = j0 + nt * 8 + cpair;
                s[nt][0] = (c0     > rowg0) ? -1e30f : s[nt][0] * SCALE_F;
                s[nt][1] = (c0 + 1 > rowg0) ? -1e30f : s[nt][1] * SCALE_F;
                s[nt][2] = (c0     > rowg1) ? -1e30f : s[nt][2] * SCALE_F;
                s[nt][3] = (c0 + 1 > rowg1) ? -1e30f : s[nt][3] * SCALE_F;
            }
        } else {
#pragma unroll
            for (int nt = 0; nt < 8; nt++)
#pragma unroll
                for (int r = 0; r < 4; r++) s[nt][r] *= SCALE_F;
        }

        // ---- online softmax (rows rowg0, rowg1) ----
        float ml0 = -1e30f, ml1 = -1e30f;
#pragma unroll
        for (int nt = 0; nt < 8; nt++) {
            ml0 = fmaxf(ml0, fmaxf(s[nt][0], s[nt][1]));
            ml1 = fmaxf(ml1, fmaxf(s[nt][2], s[nt][3]));
        }
        ml0 = fmaxf(ml0, __shfl_xor_sync(0xffffffffu, ml0, 1));
        ml0 = fmaxf(ml0, __shfl_xor_sync(0xffffffffu, ml0, 2));
        ml1 = fmaxf(ml1, __shfl_xor_sync(0xffffffffu, ml1, 1));
        ml1 = fmaxf(ml1, __shfl_xor_sync(0xffffffffu, ml1, 2));
        const float mn0 = fmaxf(m0, ml0), mn1 = fmaxf(m1, ml1);
        const float a0 = __expf(m0 - mn0), a1 = __expf(m1 - mn1);
        m0 = mn0; m1 = mn1;
        float ps0 = 0.f, ps1 = 0.f;
#pragma unroll
        for (int nt = 0; nt < 8; nt++) {
            s[nt][0] = __expf(s[nt][0] - mn0); ps0 += s[nt][0];
            s[nt][1] = __expf(s[nt][1] - mn0); ps0 += s[nt][1];
            s[nt][2] = __expf(s[nt][2] - mn1); ps1 += s[nt][2];
            s[nt][3] = __expf(s[nt][3] - mn1); ps1 += s[nt][3];
        }
        ps0 += __shfl_xor_sync(0xffffffffu, ps0, 1);
        ps0 += __shfl_xor_sync(0xffffffffu, ps0, 2);
        ps1 += __shfl_xor_sync(0xffffffffu, ps1, 1);
        ps1 += __shfl_xor_sync(0xffffffffu, ps1, 2);
        l0 = l0 * a0 + ps0;
        l1 = l1 * a1 + ps1;
#pragma unroll
        for (int nt = 0; nt < 8; nt++) {
            out[nt][0] *= a0; out[nt][1] *= a0;
            out[nt][2] *= a1; out[nt][3] *= a1;
        }

        // ---- O += P V (3-term split: Phi*Vhi + Phi*Vlo + Plo*Vhi) ----
#pragma unroll
        for (int s4 = 0; s4 < 4; s4++) {
            uint32_t ph[4], pl[4];
            {
                const float p00 = s[2 * s4][0],     p01 = s[2 * s4][1];
                const float p02 = s[2 * s4][2],     p03 = s[2 * s4][3];
                const float p10 = s[2 * s4 + 1][0], p11 = s[2 * s4 + 1][1];
                const float p12 = s[2 * s4 + 1][2], p13 = s[2 * s4 + 1][3];
                ph[0] = packbf2(p00, p01);
                ph[1] = packbf2(p02, p03);
                ph[2] = packbf2(p10, p11);
                ph[3] = packbf2(p12, p13);
                pl[0] = packbf2(p00 - __bfloat162float(__float2bfloat16(p00)),
                                p01 - __bfloat162float(__float2bfloat16(p01)));
                pl[1] = packbf2(p02 - __bfloat162float(__float2bfloat16(p02)),
                                p03 - __bfloat162float(__float2bfloat16(p03)));
                pl[2] = packbf2(p10 - __bfloat162float(__float2bfloat16(p10)),
                                p11 - __bfloat162float(__float2bfloat16(p11)));
                pl[3] = packbf2(p12 - __bfloat162float(__float2bfloat16(p12)),
                                p13 - __bfloat162float(__float2bfloat16(p13)));
            }
#pragma unroll
            for (int nt = 0; nt < 8; nt++) {
                uint32_t vh[2], vl[2];
                const int voff = SWZ128((16 * s4 + vRowL) * 128 + nt * 16);
                ldm_x2t(vh, sVh + voff);
                ldm_x2t(vl, sVl + voff);
                mma16816(out[nt], ph, vh);
                mma16816(out[nt], ph, vl);
                mma16816(out[nt], pl, vh);
            }
        }
    }

    const float inv0 = 1.0f / l0, inv1 = 1.0f / l1;
    const int t0 = rowg0, t1 = rowg1;
#pragma unroll
    for (int nt = 0; nt < 8; nt++) {
        const int col = h * 64 + nt * 8 + cpair;
        *(float2*)(attn + ((size_t)b * TT + t0) * DD + col) =
            make_float2(out[nt][0] * inv0, out[nt][1] * inv0);
        *(float2*)(attn + ((size_t)b * TT + t1) * DD + col) =
            make_float2(out[nt][2] * inv1, out[nt][3] * inv1);
    }
}

// ---------------------------------------------------------------------------
// KNN memory attention + gated combine + bf16 round-trip.
// ---------------------------------------------------------------------------
__global__ __launch_bounds__(256) void mem_combine_kernel(
    const float* __restrict__ q, const float* __restrict__ attn,
    const float* __restrict__ mem_bank, const int* __restrict__ knn_idx,
    const float* __restrict__ gate, float* __restrict__ comb) {
    const int bt = blockIdx.x;
    const int b = bt / TT;
    const int tid = threadIdx.x;
    const int h = tid >> 4, s16 = tid & 15;
    const int off = h * HDIM + s16 * 4;

    float4 q4 = *(const float4*)(q + (size_t)bt * DD + off);

    int idxs[KNN];
#pragma unroll
    for (int kk = 0; kk < KNN; kk++) idxs[kk] = knn_idx[bt * KNN + kk];

    float logit[KNN];
#pragma unroll
    for (int kk = 0; kk < KNN; kk++) {
        const float* mk = mem_bank + (((size_t)b * MM + idxs[kk]) * 2 + 0) * DD + off;
        float4 m4 = *(const float4*)mk;
        float d = q4.x * m4.x + q4.y * m4.y + q4.z * m4.z + q4.w * m4.w;
        d += __shfl_xor_sync(0xffffffffu, d, 1);
        d += __shfl_xor_sync(0xffffffffu, d, 2);
        d += __shfl_xor_sync(0xffffffffu, d, 4);
        d += __shfl_xor_sync(0xffffffffu, d, 8);
        logit[kk] = d * SCALE_F;
    }
    float m = fmaxf(logit[0], fmaxf(logit[1], logit[2]));
    float w0 = __expf(logit[0] - m);
    float w1 = __expf(logit[1] - m);
    float w2 = __expf(logit[2] - m);
    const float inv = 1.0f / (w0 + w1 + w2);
    w0 *= inv; w1 *= inv; w2 *= inv;
    const float wk[KNN] = {w0, w1, w2};

    float4 acc = {0.f, 0.f, 0.f, 0.f};
#pragma unroll
    for (int kk = 0; kk < KNN; kk++) {
        const float* mv = mem_bank + (((size_t)b * MM + idxs[kk]) * 2 + 1) * DD + off;
        float4 m4 = *(const float4*)mv;
        acc.x = fmaf(wk[kk], m4.x, acc.x);
        acc.y = fmaf(wk[kk], m4.y, acc.y);
        acc.z = fmaf(wk[kk], m4.z, acc.z);
        acc.w = fmaf(wk[kk], m4.w, acc.w);
    }

    const float g = gate[h];
    const float gi = 1.0f - g;
    float4 a4 = *(const float4*)(attn + (size_t)bt * DD + off);
    float4 out;
    out.x = __bfloat162float(__float2bfloat16(acc.x * g + a4.x * gi));
    out.y = __bfloat162float(__float2bfloat16(acc.y * g + a4.y * gi));
    out.z = __bfloat162float(__float2bfloat16(acc.z * g + a4.z * gi));
    out.w = __bfloat162float(__float2bfloat16(acc.w * g + a4.w * gi));
    *(float4*)(comb + (size_t)bt * DD + off) = out;
}

// ---------------------------------------------------------------------------
extern "C" void kernel_launch(void* const* d_in, const int* in_sizes, int n_in,
                              void* d_out, int out_size) {
    const float* x    = (const float*)d_in[0];
    const float* Wq   = (const float*)d_in[1];
    const float* bq   = (const float*)d_in[2];
    const float* Wk   = (const float*)d_in[3];
    const float* bk   = (const float*)d_in[4];
    const float* Wv   = (const float*)d_in[5];
    const float* bv   = (const float*)d_in[6];
    const float* Wo   = (const float*)d_in[7];
    const float* bo   = (const float*)d_in[8];
    const float* gate = (const float*)d_in[9];
    const float* memb = (const float*)d_in[10];
    const int*   knn  = (const int*)d_in[11];
    float* out = (float*)d_out;

    float *q, *k, *v, *attn, *comb;
    __nv_bfloat16 *x2, *w2, *qs, *ks, *vs;
    cudaGetSymbolAddress((void**)&q, g_q);
    cudaGetSymbolAddress((void**)&k, g_k);
    cudaGetSymbolAddress((void**)&v, g_v);
    cudaGetSymbolAddress((void**)&attn, g_attn);
    cudaGetSymbolAddress((void**)&comb, g_comb);
    cudaGetSymbolAddress((void**)&x2, g_x2);
    cudaGetSymbolAddress((void**)&w2, g_w2);
    cudaGetSymbolAddress((void**)&qs, g_qs);
    cudaGetSymbolAddress((void**)&ks, g_ks);
    cudaGetSymbolAddress((void**)&vs, g_vs);

    cudaFuncSetAttribute(flash_mma_kernel,
                         cudaFuncAttributeMaxDynamicSharedMemorySize, FLM_SMEM);

    const dim3 gg(DD / 128, NROWS / 128);   // (8, 32)

    split3_kernel<<<NROWS * DD / 256, 256>>>(x, x2, 0);

    split3_kernel<<<DD * DD / 256, 256>>>(Wq, w2, 1);
    gemm_mma_kernel<<<gg, 256>>>(x2, w2, bq, q);
    split3_kernel<<<DD * DD / 256, 256>>>(Wk, w2, 1);
    gemm_mma_kernel<<<gg, 256>>>(x2, w2, bk, k);
    split3_kernel<<<DD * DD / 256, 256>>>(Wv, w2, 1);
    gemm_mma_kernel<<<gg, 256>>>(x2, w2, bv, v);

    norm_split_kernel<<<NROWS, 256>>>(q, qs, 1, 1);   // normalize + writeback
    norm_split_kernel<<<NROWS, 256>>>(k, ks, 1, 0);
    norm_split_kernel<<<NROWS, 256>>>(v, vs, 0, 0);

    flash_mma_kernel<<<dim3(16, HH, BB), 256, FLM_SMEM>>>(qs, ks, vs, attn);

    mem_combine_kernel<<<NROWS, 256>>>(q, attn, memb, knn, gate, comb);

    split3_kernel<<<NROWS * DD / 256, 256>>>(comb, x2, 0);
    split3_kernel<<<DD * DD / 256, 256>>>(Wo, w2, 1);
    gemm_mma_kernel<<<gg, 256>>>(x2, w2, bo, out);
}

// round 9
// speedup vs baseline: 3.8402x; 1.2200x over previous
#include <cuda_runtime.h>
#include <cuda_bf16.h>
#include <math.h>
#include <stdint.h>

#define BB 2
#define TT 2048
#define DD 1024
#define HH 16
#define KNN 3
#define MM 16384
#define HDIM 64
#define NROWS (BB*TT)         // 4096
#define SCALE_F 4096.0f       // D * sqrt(H)
#define K3 3072               // split-concatenated K
#define PLANE (NROWS * DD)    // hi plane size; lo at +PLANE

// ---------------- scratch (static device globals; no runtime allocation) ----
__device__ float g_q[NROWS * DD];
__device__ float g_k[NROWS * DD];
__device__ float g_v[NROWS * DD];
__device__ float g_attn[NROWS * DD];
__device__ __nv_bfloat16 g_x2[NROWS * K3];     // split activations (reused for comb)
__device__ __nv_bfloat16 g_wqkv[3 * DD * K3];  // split Wq|Wk|Wv
__device__ __nv_bfloat16 g_qs[2 * PLANE];      // per-head (b,h,t,64) hi/lo
__device__ __nv_bfloat16 g_ks[2 * PLANE];
__device__ __nv_bfloat16 g_vs[2 * PLANE];

#define SWZ128(off) ((off) ^ (((off) >> 3) & 0x70))

__device__ __forceinline__ uint32_t smem_u32(const void* p) {
    uint32_t a;
    asm("{ .reg .u64 t; cvta.to.shared.u64 t, %1; cvt.u32.u64 %0, t; }"
        : "=r"(a) : "l"(p));
    return a;
}
__device__ __forceinline__ void cp_async16(uint32_t dst, const void* src) {
    asm volatile("cp.async.cg.shared.global [%0], [%1], 16;"
                 :: "r"(dst), "l"(src) : "memory");
}
__device__ __forceinline__ void cp_commit() {
    asm volatile("cp.async.commit_group;" ::: "memory");
}
__device__ __forceinline__ void ldm_x4(uint32_t* r, uint32_t addr) {
    asm volatile("ldmatrix.sync.aligned.m8n8.x4.shared.b16 {%0,%1,%2,%3}, [%4];"
                 : "=r"(r[0]), "=r"(r[1]), "=r"(r[2]), "=r"(r[3]) : "r"(addr));
}
__device__ __forceinline__ void ldm_x2(uint32_t* r, uint32_t addr) {
    asm volatile("ldmatrix.sync.aligned.m8n8.x2.shared.b16 {%0,%1}, [%2];"
                 : "=r"(r[0]), "=r"(r[1]) : "r"(addr));
}
__device__ __forceinline__ void ldm_x2t(uint32_t* r, uint32_t addr) {
    asm volatile("ldmatrix.sync.aligned.m8n8.x2.trans.shared.b16 {%0,%1}, [%2];"
                 : "=r"(r[0]), "=r"(r[1]) : "r"(addr));
}
__device__ __forceinline__ void mma16816(float* d, const uint32_t* a, const uint32_t* b) {
    asm volatile(
        "mma.sync.aligned.m16n8k16.row.col.f32.bf16.bf16.f32 "
        "{%0,%1,%2,%3}, {%4,%5,%6,%7}, {%8,%9}, {%0,%1,%2,%3};"
        : "+f"(d[0]), "+f"(d[1]), "+f"(d[2]), "+f"(d[3])
        : "r"(a[0]), "r"(a[1]), "r"(a[2]), "r"(a[3]), "r"(b[0]), "r"(b[1]));
}
__device__ __forceinline__ uint32_t packbf2(float lo, float hi) {
    uint32_t r;
    asm("cvt.rn.bf16x2.f32 %0, %1, %2;" : "=r"(r) : "f"(hi), "f"(lo));
    return r;
}

// ---------------------------------------------------------------------------
// Split fp32 -> [hi,hi,lo] (mode 0, activations) or [hi,lo,hi] (mode 1, W)
// ---------------------------------------------------------------------------
__global__ __launch_bounds__(256) void split3_kernel(
    const float* __restrict__ X, __nv_bfloat16* __restrict__ Y, int modeB) {
    const int idx = blockIdx.x * 256 + threadIdx.x;
    const int row = idx >> 10, col = idx & 1023;
    float v = X[idx];
    __nv_bfloat16 h = __float2bfloat16(v);
    __nv_bfloat16 l = __float2bfloat16(v - __bfloat162float(h));
    __nv_bfloat16* y = Y + (size_t)row * K3 + col;
    y[0] = h;
    y[1024] = modeB ? l : h;
    y[2048] = modeB ? h : l;
}

// ---------------------------------------------------------------------------
// cp.async double-buffered bf16 HMMA GEMM, multi-output.
// global col = blockIdx.x*128; mat = col>>10 selects (bias, C) pair.
// B2 rows indexed by global col (so concat weights work directly).
// ---------------------------------------------------------------------------
#define GEMM_NCHUNK (K3 / 64)       // 48
#define GEMM_SMEM 65536

__global__ __launch_bounds__(256) void gemm_mma_kernel(
    const __nv_bfloat16* __restrict__ A2, const __nv_bfloat16* __restrict__ B2,
    const float* __restrict__ bias0, const float* __restrict__ bias1,
    const float* __restrict__ bias2,
    float* __restrict__ C0, float* __restrict__ C1, float* __restrict__ C2) {
    extern __shared__ char smem[];
    const uint32_t s0 = smem_u32(smem);
    // layout: A buf0 @0, A buf1 @16384, B buf0 @32768, B buf1 @49152

    const int tid = threadIdx.x;
    const int wid = tid >> 5, lane = tid & 31;
    const int warpM = wid >> 2, warpN = wid & 3;
    const int bi = blockIdx.y * 128;
    const int gcol = blockIdx.x * 128;             // global (concat) column
    const int mat = gcol >> 10;
    const float* bias = (mat == 0) ? bias0 : (mat == 1) ? bias1 : bias2;
    float* C = (mat == 0) ? C0 : (mat == 1) ? C1 : C2;
    const int bj = gcol & 1023;                    // column within output matrix

    const int rowL = tid >> 3;       // 0..31
    const int c16 = tid & 7;

    float acc[4][4][4];
#pragma unroll
    for (int i = 0; i < 4; i++)
#pragma unroll
        for (int j = 0; j < 4; j++)
#pragma unroll
            for (int r = 0; r < 4; r++) acc[i][j][r] = 0.f;

    const int aRow = warpM * 64 + (lane & 15);
    const int aHalf = (lane >> 4) * 16;
    const int bRow = warpN * 32 + (lane & 7);
    const int bHalf = ((lane >> 3) & 1) * 16;

    // per-thread smem store offsets (pre-swizzled), row strided by 32
    int soff[4];
#pragma unroll
    for (int i = 0; i < 4; i++)
        soff[i] = SWZ128((rowL + i * 32) * 128 + c16 * 16);
    const __nv_bfloat16* aSrc = A2 + (size_t)(bi + rowL) * K3 + c16 * 8;
    const __nv_bfloat16* bSrc = B2 + (size_t)(gcol + rowL) * K3 + c16 * 8;

#define GEMM_ISSUE(c, s) do {                                                  \
    const int _k0 = (c) * 64;                                                  \
    const uint32_t _da = s0 + (s) * 16384;                                     \
    const uint32_t _db = s0 + 32768 + (s) * 16384;                             \
    _Pragma("unroll")                                                          \
    for (int _i = 0; _i < 4; _i++) {                                           \
        cp_async16(_da + soff[_i], aSrc + (size_t)_i * 32 * K3 + _k0);         \
        cp_async16(_db + soff[_i], bSrc + (size_t)_i * 32 * K3 + _k0);         \
    }                                                                          \
    cp_commit();                                                               \
} while (0)

    GEMM_ISSUE(0, 0);
    GEMM_ISSUE(1, 1);

    for (int c = 0; c < GEMM_NCHUNK; c++) {
        if (c + 1 < GEMM_NCHUNK)
            asm volatile("cp.async.wait_group 1;" ::: "memory");
        else
            asm volatile("cp.async.wait_group 0;" ::: "memory");
        __syncthreads();
        const int s = c & 1;
        const uint32_t sa = s0 + s * 16384;
        const uint32_t sb = s0 + 32768 + s * 16384;
#pragma unroll
        for (int st = 0; st < 4; st++) {
            uint32_t af[4][4], bf[4][2];
#pragma unroll
            for (int i = 0; i < 4; i++)
                ldm_x4(af[i], sa + SWZ128((aRow + i * 16) * 128 + st * 32 + aHalf));
#pragma unroll
            for (int j = 0; j < 4; j++)
                ldm_x2(bf[j], sb + SWZ128((bRow + j * 8) * 128 + st * 32 + bHalf));
#pragma unroll
            for (int i = 0; i < 4; i++)
#pragma unroll
                for (int j = 0; j < 4; j++)
                    mma16816(acc[i][j], af[i], bf[j]);
        }
        __syncthreads();
        if (c + 2 < GEMM_NCHUNK) GEMM_ISSUE(c + 2, s);
    }
#undef GEMM_ISSUE

#pragma unroll
    for (int i = 0; i < 4; i++) {
        const int r0 = bi + warpM * 64 + i * 16 + (lane >> 2);
#pragma unroll
        for (int j = 0; j < 4; j++) {
            const int c0 = bj + warpN * 32 + j * 8 + (lane & 3) * 2;
            const float b0 = bias[c0], b1 = bias[c0 + 1];
            float2 o0 = make_float2(acc[i][j][0] + b0, acc[i][j][1] + b1);
            float2 o1 = make_float2(acc[i][j][2] + b0, acc[i][j][3] + b1);
            *(float2*)(C + (size_t)r0 * DD + c0) = o0;
            *(float2*)(C + (size_t)(r0 + 8) * DD + c0) = o1;
        }
    }
}

// ---------------------------------------------------------------------------
// Optional row L2-normalize + hi/lo bf16 split into per-head (b,h,t,64) planes.
// ---------------------------------------------------------------------------
__global__ __launch_bounds__(256) void norm_split_kernel(
    float* __restrict__ p, __nv_bfloat16* __restrict__ Y,
    int do_norm, int writeback) {
    const int row = blockIdx.x;
    const int b = row >> 11, t = row & 2047;
    const int tid = threadIdx.x;
    __shared__ float red[8];
    float4 a = *(const float4*)(p + (size_t)row * DD + tid * 4);
    if (do_norm) {
        float ss = a.x * a.x + a.y * a.y + a.z * a.z + a.w * a.w;
#pragma unroll
        for (int m = 16; m; m >>= 1) ss += __shfl_xor_sync(0xffffffffu, ss, m);
        if ((tid & 31) == 0) red[tid >> 5] = ss;
        __syncthreads();
        float tot = red[0] + red[1] + red[2] + red[3] +
                    red[4] + red[5] + red[6] + red[7];
        float inv = 1.0f / fmaxf(sqrtf(tot), 1e-12f);
        a.x *= inv; a.y *= inv; a.z *= inv; a.w *= inv;
        if (writeback)
            *(float4*)(p + (size_t)row * DD + tid * 4) = a;
    }
    const int h = tid >> 4;
    const int dh = (tid & 15) * 4;
    __nv_bfloat16* dst = Y + ((size_t)(b * HH + h) * TT + t) * 64 + dh;
    __nv_bfloat16 hi[4], lo[4];
    const float* av = (const float*)&a;
#pragma unroll
    for (int i = 0; i < 4; i++) {
        hi[i] = __float2bfloat16(av[i]);
        lo[i] = __float2bfloat16(av[i] - __bfloat162float(hi[i]));
    }
    *(uint2*)dst = *(const uint2*)hi;
    *(uint2*)(dst + PLANE) = *(const uint2*)lo;
}

// ---------------------------------------------------------------------------
// Flash attention via bf16 mma with hi/lo 3-term splits. (unchanged from R7)
// ---------------------------------------------------------------------------
#define FLM_SMEM 65536

__global__ __launch_bounds__(256) void flash_mma_kernel(
    const __nv_bfloat16* __restrict__ qs, const __nv_bfloat16* __restrict__ ks,
    const __nv_bfloat16* __restrict__ vs, float* __restrict__ attn) {
    extern __shared__ char sm[];
    const uint32_t sQh = smem_u32(sm);
    const uint32_t sQl = sQh + 16384;
    const uint32_t sKh = sQh + 32768;
    const uint32_t sKl = sQh + 40960;
    const uint32_t sVh = sQh + 49152;
    const uint32_t sVl = sQh + 57344;

    const int qt = 15 - blockIdx.x;
    const int h = blockIdx.y, b = blockIdx.z;
    const int tid = threadIdx.x, wid = tid >> 5, lane = tid & 31;
    const size_t hb = ((size_t)(b * HH + h)) * TT * 64;

    {
        const int row = tid >> 1, part = tid & 1;
        const __nv_bfloat16* srcH = qs + hb + (size_t)(qt * 128 + row) * 64 + part * 32;
        const __nv_bfloat16* srcL = srcH + PLANE;
#pragma unroll
        for (int i = 0; i < 4; i++) {
            const int off = SWZ128(row * 128 + part * 64 + i * 16);
            *(uint4*)(sm + off) = *(const uint4*)(srcH + i * 8);
            *(uint4*)(sm + 16384 + off) = *(const uint4*)(srcL + i * 8);
        }
    }

    float out[8][4];
#pragma unroll
    for (int nt = 0; nt < 8; nt++)
#pragma unroll
        for (int r = 0; r < 4; r++) out[nt][r] = 0.f;
    float m0 = -1e30f, m1 = -1e30f, l0 = 0.f, l1 = 0.f;

    const int r4 = lane >> 2;
    const int cpair = (lane & 3) * 2;
    const int rowg0 = qt * 128 + wid * 16 + r4;
    const int rowg1 = rowg0 + 8;
    const int rowmax = qt * 128 + wid * 16 + 15;
    const int warpmin = qt * 128 + wid * 16;

    const int qRow = wid * 16 + (lane & 15);
    const int qHalf = (lane >> 4) * 16;
    const int kRowL = lane & 7;
    const int kHalf = ((lane >> 3) & 1) * 16;
    const int vRowL = (lane & 7) + ((lane >> 3) & 1) * 8;

    const int ktmax = 2 * qt + 1;
    for (int kt = 0; kt <= ktmax; kt++) {
        const int j0 = kt * 64;
        __syncthreads();
        {
            const int row = tid >> 2, c = tid & 3;
            const size_t src = hb + (size_t)(j0 + row) * 64 + c * 16;
            const int d0 = SWZ128(row * 128 + c * 32);
            const int d1 = SWZ128(row * 128 + c * 32 + 16);
            *(uint4*)(sm + 32768 + d0) = *(const uint4*)(ks + src);
            *(uint4*)(sm + 32768 + d1) = *(const uint4*)(ks + src + 8);
            *(uint4*)(sm + 40960 + d0) = *(const uint4*)(ks + PLANE + src);
            *(uint4*)(sm + 40960 + d1) = *(const uint4*)(ks + PLANE + src + 8);
            *(uint4*)(sm + 49152 + d0) = *(const uint4*)(vs + src);
            *(uint4*)(sm + 49152 + d1) = *(const uint4*)(vs + src + 8);
            *(uint4*)(sm + 57344 + d0) = *(const uint4*)(vs + PLANE + src);
            *(uint4*)(sm + 57344 + d1) = *(const uint4*)(vs + PLANE + src + 8);
        }
        __syncthreads();
        if (j0 > rowmax) continue;

        float s[8][4];
#pragma unroll
        for (int nt = 0; nt < 8; nt++)
#pragma unroll
            for (int r = 0; r < 4; r++) s[nt][r] = 0.f;
#pragma unroll
        for (int s4 = 0; s4 < 4; s4++) {
            uint32_t ah[4], al[4];
            ldm_x4(ah, sQh + SWZ128(qRow * 128 + s4 * 32 + qHalf));
            ldm_x4(al, sQl + SWZ128(qRow * 128 + s4 * 32 + qHalf));
#pragma unroll
            for (int nt = 0; nt < 8; nt++) {
                uint32_t bh[2], bl[2];
                const int boff = SWZ128((nt * 8 + kRowL) * 128 + s4 * 32 + kHalf);
                ldm_x2(bh, sKh + boff);
                ldm_x2(bl, sKl + boff);
                mma16816(s[nt], ah, bh);
                mma16816(s[nt], al, bh);
                mma16816(s[nt], ah, bl);
            }
        }

        if (j0 + 63 > warpmin) {
#pragma unroll
            for (int nt = 0; nt < 8; nt++) {
                const int c0 = j0 + nt * 8 + cpair;
                s[nt][0] = (c0     > rowg0) ? -1e30f : s[nt][0] * SCALE_F;
                s[nt][1] = (c0 + 1 > rowg0) ? -1e30f : s[nt][1] * SCALE_F;
                s[nt][2] = (c0     > rowg1) ? -1e30f : s[nt][2] * SCALE_F;
                s[nt][3] = (c0 + 1 > rowg1) ? -1e30f : s[nt][3] * SCALE_F;
            }
        } else {
#pragma unroll
            for (int nt = 0; nt < 8; nt++)
#pragma unroll
                for (int r = 0; r < 4; r++) s[nt][r] *= SCALE_F;
        }

        float ml0 = -1e30f, ml1 = -1e30f;
#pragma unroll
        for (int nt = 0; nt < 8; nt++) {
            ml0 = fmaxf(ml0, fmaxf(s[nt][0], s[nt][1]));
            ml1 = fmaxf(ml1, fmaxf(s[nt][2], s[nt][3]));
        }
        ml0 = fmaxf(ml0, __shfl_xor_sync(0xffffffffu, ml0, 1));
        ml0 = fmaxf(ml0, __shfl_xor_sync(0xffffffffu, ml0, 2));
        ml1 = fmaxf(ml1, __shfl_xor_sync(0xffffffffu, ml1, 1));
        ml1 = fmaxf(ml1, __shfl_xor_sync(0xffffffffu, ml1, 2));
        const float mn0 = fmaxf(m0, ml0), mn1 = fmaxf(m1, ml1);
        const float a0 = __expf(m0 - mn0), a1 = __expf(m1 - mn1);
        m0 = mn0; m1 = mn1;
        float ps0 = 0.f, ps1 = 0.f;
#pragma unroll
        for (int nt = 0; nt < 8; nt++) {
            s[nt][0] = __expf(s[nt][0] - mn0); ps0 += s[nt][0];
            s[nt][1] = __expf(s[nt][1] - mn0); ps0 += s[nt][1];
            s[nt][2] = __expf(s[nt][2] - mn1); ps1 += s[nt][2];
            s[nt][3] = __expf(s[nt][3] - mn1); ps1 += s[nt][3];
        }
        ps0 += __shfl_xor_sync(0xffffffffu, ps0, 1);
        ps0 += __shfl_xor_sync(0xffffffffu, ps0, 2);
        ps1 += __shfl_xor_sync(0xffffffffu, ps1, 1);
        ps1 += __shfl_xor_sync(0xffffffffu, ps1, 2);
        l0 = l0 * a0 + ps0;
        l1 = l1 * a1 + ps1;
#pragma unroll
        for (int nt = 0; nt < 8; nt++) {
            out[nt][0] *= a0; out[nt][1] *= a0;
            out[nt][2] *= a1; out[nt][3] *= a1;
        }

#pragma unroll
        for (int s4 = 0; s4 < 4; s4++) {
            uint32_t ph[4], pl[4];
            {
                const float p00 = s[2 * s4][0],     p01 = s[2 * s4][1];
                const float p02 = s[2 * s4][2],     p03 = s[2 * s4][3];
                const float p10 = s[2 * s4 + 1][0], p11 = s[2 * s4 + 1][1];
                const float p12 = s[2 * s4 + 1][2], p13 = s[2 * s4 + 1][3];
                ph[0] = packbf2(p00, p01);
                ph[1] = packbf2(p02, p03);
                ph[2] = packbf2(p10, p11);
                ph[3] = packbf2(p12, p13);
                pl[0] = packbf2(p00 - __bfloat162float(__float2bfloat16(p00)),
                                p01 - __bfloat162float(__float2bfloat16(p01)));
                pl[1] = packbf2(p02 - __bfloat162float(__float2bfloat16(p02)),
                                p03 - __bfloat162float(__float2bfloat16(p03)));
                pl[2] = packbf2(p10 - __bfloat162float(__float2bfloat16(p10)),
                                p11 - __bfloat162float(__float2bfloat16(p11)));
                pl[3] = packbf2(p12 - __bfloat162float(__float2bfloat16(p12)),
                                p13 - __bfloat162float(__float2bfloat16(p13)));
            }
#pragma unroll
            for (int nt = 0; nt < 8; nt++) {
                uint32_t vh[2], vl[2];
                const int voff = SWZ128((16 * s4 + vRowL) * 128 + nt * 16);
                ldm_x2t(vh, sVh + voff);
                ldm_x2t(vl, sVl + voff);
                mma16816(out[nt], ph, vh);
                mma16816(out[nt], ph, vl);
                mma16816(out[nt], pl, vh);
            }
        }
    }

    const float inv0 = 1.0f / l0, inv1 = 1.0f / l1;
#pragma unroll
    for (int nt = 0; nt < 8; nt++) {
        const int col = h * 64 + nt * 8 + cpair;
        *(float2*)(attn + ((size_t)b * TT + rowg0) * DD + col) =
            make_float2(out[nt][0] * inv0, out[nt][1] * inv0);
        *(float2*)(attn + ((size_t)b * TT + rowg1) * DD + col) =
            make_float2(out[nt][2] * inv1, out[nt][3] * inv1);
    }
}

// ---------------------------------------------------------------------------
// KNN memory attention + gated combine + bf16 round-trip,
// writing the split [hi,hi,lo] activation planes directly (fused split3).
// ---------------------------------------------------------------------------
__global__ __launch_bounds__(256) void mem_combine_split_kernel(
    const float* __restrict__ q, const float* __restrict__ attn,
    const float* __restrict__ mem_bank, const int* __restrict__ knn_idx,
    const float* __restrict__ gate, __nv_bfloat16* __restrict__ Y) {
    const int bt = blockIdx.x;
    const int b = bt / TT;
    const int tid = threadIdx.x;
    const int h = tid >> 4, s16 = tid & 15;
    const int off = h * HDIM + s16 * 4;

    float4 q4 = *(const float4*)(q + (size_t)bt * DD + off);

    int idxs[KNN];
#pragma unroll
    for (int kk = 0; kk < KNN; kk++) idxs[kk] = knn_idx[bt * KNN + kk];

    float logit[KNN];
#pragma unroll
    for (int kk = 0; kk < KNN; kk++) {
        const float* mk = mem_bank + (((size_t)b * MM + idxs[kk]) * 2 + 0) * DD + off;
        float4 m4 = *(const float4*)mk;
        float d = q4.x * m4.x + q4.y * m4.y + q4.z * m4.z + q4.w * m4.w;
        d += __shfl_xor_sync(0xffffffffu, d, 1);
        d += __shfl_xor_sync(0xffffffffu, d, 2);
        d += __shfl_xor_sync(0xffffffffu, d, 4);
        d += __shfl_xor_sync(0xffffffffu, d, 8);
        logit[kk] = d * SCALE_F;
    }
    float m = fmaxf(logit[0], fmaxf(logit[1], logit[2]));
    float w0 = __expf(logit[0] - m);
    float w1 = __expf(logit[1] - m);
    float w2 = __expf(logit[2] - m);
    const float inv = 1.0f / (w0 + w1 + w2);
    w0 *= inv; w1 *= inv; w2 *= inv;
    const float wk[KNN] = {w0, w1, w2};

    float4 acc = {0.f, 0.f, 0.f, 0.f};
#pragma unroll
    for (int kk = 0; kk < KNN; kk++) {
        const float* mv = mem_bank + (((size_t)b * MM + idxs[kk]) * 2 + 1) * DD + off;
        float4 m4 = *(const float4*)mv;
        acc.x = fmaf(wk[kk], m4.x, acc.x);
        acc.y = fmaf(wk[kk], m4.y, acc.y);
        acc.z = fmaf(wk[kk], m4.z, acc.z);
        acc.w = fmaf(wk[kk], m4.w, acc.w);
    }

    const float g = gate[h];
    const float gi = 1.0f - g;
    float4 a4 = *(const float4*)(attn + (size_t)bt * DD + off);
    float cv[4];
    cv[0] = __bfloat162float(__float2bfloat16(acc.x * g + a4.x * gi));
    cv[1] = __bfloat162float(__float2bfloat16(acc.y * g + a4.y * gi));
    cv[2] = __bfloat162float(__float2bfloat16(acc.z * g + a4.z * gi));
    cv[3] = __bfloat162float(__float2bfloat16(acc.w * g + a4.w * gi));

    __nv_bfloat16 hi[4], lo[4];
#pragma unroll
    for (int i = 0; i < 4; i++) {
        hi[i] = __float2bfloat16(cv[i]);
        lo[i] = __float2bfloat16(cv[i] - __bfloat162float(hi[i]));
    }
    __nv_bfloat16* y = Y + (size_t)bt * K3 + off;
    *(uint2*)y = *(const uint2*)hi;
    *(uint2*)(y + 1024) = *(const uint2*)hi;
    *(uint2*)(y + 2048) = *(const uint2*)lo;
}

// ---------------------------------------------------------------------------
extern "C" void kernel_launch(void* const* d_in, const int* in_sizes, int n_in,
                              void* d_out, int out_size) {
    const float* x    = (const float*)d_in[0];
    const float* Wq   = (const float*)d_in[1];
    const float* bq   = (const float*)d_in[2];
    const float* Wk   = (const float*)d_in[3];
    const float* bk   = (const float*)d_in[4];
    const float* Wv   = (const float*)d_in[5];
    const float* bv   = (const float*)d_in[6];
    const float* Wo   = (const float*)d_in[7];
    const float* bo   = (const float*)d_in[8];
    const float* gate = (const float*)d_in[9];
    const float* memb = (const float*)d_in[10];
    const int*   knn  = (const int*)d_in[11];
    float* out = (float*)d_out;

    float *q, *k, *v, *attn;
    __nv_bfloat16 *x2, *wqkv, *qs, *ks, *vs;
    cudaGetSymbolAddress((void**)&q, g_q);
    cudaGetSymbolAddress((void**)&k, g_k);
    cudaGetSymbolAddress((void**)&v, g_v);
    cudaGetSymbolAddress((void**)&attn, g_attn);
    cudaGetSymbolAddress((void**)&x2, g_x2);
    cudaGetSymbolAddress((void**)&wqkv, g_wqkv);
    cudaGetSymbolAddress((void**)&qs, g_qs);
    cudaGetSymbolAddress((void**)&ks, g_ks);
    cudaGetSymbolAddress((void**)&vs, g_vs);

    cudaFuncSetAttribute(flash_mma_kernel,
                         cudaFuncAttributeMaxDynamicSharedMemorySize, FLM_SMEM);
    cudaFuncSetAttribute(gemm_mma_kernel,
                         cudaFuncAttributeMaxDynamicSharedMemorySize, GEMM_SMEM);

    // split activations + concatenated QKV weights
    split3_kernel<<<NROWS * DD / 256, 256>>>(x, x2, 0);
    split3_kernel<<<DD * DD / 256, 256>>>(Wq, wqkv, 1);
    split3_kernel<<<DD * DD / 256, 256>>>(Wk, wqkv + (size_t)DD * K3, 1);
    split3_kernel<<<DD * DD / 256, 256>>>(Wv, wqkv + (size_t)2 * DD * K3, 1);

    // fused QKV GEMM: grid (24, 32)
    gemm_mma_kernel<<<dim3(24, NROWS / 128), 256, GEMM_SMEM>>>(
        x2, wqkv, bq, bk, bv, q, k, v);

    norm_split_kernel<<<NROWS, 256>>>(q, qs, 1, 1);   // normalize + writeback
    norm_split_kernel<<<NROWS, 256>>>(k, ks, 1, 0);
    norm_split_kernel<<<NROWS, 256>>>(v, vs, 0, 0);

    flash_mma_kernel<<<dim3(16, HH, BB), 256, FLM_SMEM>>>(qs, ks, vs, attn);

    // fused KNN combine + split (writes x2 directly)
    mem_combine_split_kernel<<<NROWS, 256>>>(q, attn, memb, knn, gate, x2);

    // O projection (single-matrix case of the multi-output GEMM)
    split3_kernel<<<DD * DD / 256, 256>>>(Wo, wqkv, 1);
    gemm_mma_kernel<<<dim3(8, NROWS / 128), 256, GEMM_SMEM>>>(
        x2, wqkv, bo, bo, bo, out, out, out);
}

// round 12
// speedup vs baseline: 3.8496x; 1.0025x over previous
#include <cuda_runtime.h>
#include <cuda_bf16.h>
#include <math.h>
#include <stdint.h>

#define BB 2
#define TT 2048
#define DD 1024
#define HH 16
#define KNN 3
#define MM 16384
#define HDIM 64
#define NROWS (BB*TT)         // 4096
#define SCALE_F 4096.0f       // D * sqrt(H)
#define K3 3072               // split-concatenated K
#define PLANE (NROWS * DD)    // hi plane size; lo at +PLANE

// ---------------- scratch (static device globals; no runtime allocation) ----
__device__ float g_q[NROWS * DD];
__device__ float g_k[NROWS * DD];
__device__ float g_v[NROWS * DD];
__device__ float g_attn[NROWS * DD];
__device__ __nv_bfloat16 g_x2[NROWS * K3];       // split activations (reused for comb)
__device__ __nv_bfloat16 g_wqkv[4 * DD * K3];    // split Wq|Wk|Wv|Wo
__device__ __nv_bfloat16 g_qs[2 * PLANE];        // per-head (b,h,t,64) hi/lo
__device__ __nv_bfloat16 g_ks[2 * PLANE];
__device__ __nv_bfloat16 g_vs[2 * PLANE];

#define SWZ128(off) ((off) ^ (((off) >> 3) & 0x70))

__device__ __forceinline__ uint32_t smem_u32(const void* p) {
    uint32_t a;
    asm("{ .reg .u64 t; cvta.to.shared.u64 t, %1; cvt.u32.u64 %0, t; }"
        : "=r"(a) : "l"(p));
    return a;
}
__device__ __forceinline__ void cp_async16(uint32_t dst, const void* src) {
    asm volatile("cp.async.cg.shared.global [%0], [%1], 16;"
                 :: "r"(dst), "l"(src) : "memory");
}
__device__ __forceinline__ void cp_commit() {
    asm volatile("cp.async.commit_group;" ::: "memory");
}
__device__ __forceinline__ void ldm_x4(uint32_t* r, uint32_t addr) {
    asm volatile("ldmatrix.sync.aligned.m8n8.x4.shared.b16 {%0,%1,%2,%3}, [%4];"
                 : "=r"(r[0]), "=r"(r[1]), "=r"(r[2]), "=r"(r[3]) : "r"(addr));
}
__device__ __forceinline__ void ldm_x2(uint32_t* r, uint32_t addr) {
    asm volatile("ldmatrix.sync.aligned.m8n8.x2.shared.b16 {%0,%1}, [%2];"
                 : "=r"(r[0]), "=r"(r[1]) : "r"(addr));
}
__device__ __forceinline__ void ldm_x2t(uint32_t* r, uint32_t addr) {
    asm volatile("ldmatrix.sync.aligned.m8n8.x2.trans.shared.b16 {%0,%1}, [%2];"
                 : "=r"(r[0]), "=r"(r[1]) : "r"(addr));
}
__device__ __forceinline__ void mma16816(float* d, const uint32_t* a, const uint32_t* b) {
    asm volatile(
        "mma.sync.aligned.m16n8k16.row.col.f32.bf16.bf16.f32 "
        "{%0,%1,%2,%3}, {%4,%5,%6,%7}, {%8,%9}, {%0,%1,%2,%3};"
        : "+f"(d[0]), "+f"(d[1]), "+f"(d[2]), "+f"(d[3])
        : "r"(a[0]), "r"(a[1]), "r"(a[2]), "r"(a[3]), "r"(b[0]), "r"(b[1]));
}
__device__ __forceinline__ uint32_t packbf2(float lo, float hi) {
    uint32_t r;
    asm("cvt.rn.bf16x2.f32 %0, %1, %2;" : "=r"(r) : "f"(hi), "f"(lo));
    return r;
}

// ---------------------------------------------------------------------------
// One-shot split: x -> x2 [hi,hi,lo]; Wq/Wk/Wv/Wo -> wqkv slots [hi,lo,hi].
// grid.x = 16384 (x) + 4*4096 (weights) = 32768 blocks of 256.
// ---------------------------------------------------------------------------
__global__ __launch_bounds__(256) void split_all_kernel(
    const float* __restrict__ x,
    const float* __restrict__ Wq, const float* __restrict__ Wk,
    const float* __restrict__ Wv, const float* __restrict__ Wo,
    __nv_bfloat16* __restrict__ x2, __nv_bfloat16* __restrict__ wqkv) {
    const int blk = blockIdx.x;
    const float* src;
    __nv_bfloat16* dstbase;
    int idx, modeB;
    if (blk < 16384) {
        src = x; dstbase = x2; modeB = 0;
        idx = blk * 256 + threadIdx.x;
    } else {
        const int t = blk - 16384;
        const int w = t >> 12;                 // 0..3
        src = (w == 0) ? Wq : (w == 1) ? Wk : (w == 2) ? Wv : Wo;
        dstbase = wqkv + (size_t)w * DD * K3;
        modeB = 1;
        idx = (t & 4095) * 256 + threadIdx.x;
    }
    const int row = idx >> 10, col = idx & 1023;
    float v = src[idx];
    __nv_bfloat16 h = __float2bfloat16(v);
    __nv_bfloat16 l = __float2bfloat16(v - __bfloat162float(h));
    __nv_bfloat16* y = dstbase + (size_t)row * K3 + col;
    y[0] = h;
    y[1024] = modeB ? l : h;
    y[2048] = modeB ? h : l;
}

// ---------------------------------------------------------------------------
// cp.async double-buffered bf16 HMMA GEMM, multi-output (unchanged from R9).
// ---------------------------------------------------------------------------
#define GEMM_NCHUNK (K3 / 64)       // 48
#define GEMM_SMEM 65536

__global__ __launch_bounds__(256) void gemm_mma_kernel(
    const __nv_bfloat16* __restrict__ A2, const __nv_bfloat16* __restrict__ B2,
    const float* __restrict__ bias0, const float* __restrict__ bias1,
    const float* __restrict__ bias2,
    float* __restrict__ C0, float* __restrict__ C1, float* __restrict__ C2) {
    extern __shared__ char smem[];
    const uint32_t s0 = smem_u32(smem);

    const int tid = threadIdx.x;
    const int wid = tid >> 5, lane = tid & 31;
    const int warpM = wid >> 2, warpN = wid & 3;
    const int bi = blockIdx.y * 128;
    const int gcol = blockIdx.x * 128;
    const int mat = gcol >> 10;
    const float* bias = (mat == 0) ? bias0 : (mat == 1) ? bias1 : bias2;
    float* C = (mat == 0) ? C0 : (mat == 1) ? C1 : C2;
    const int bj = gcol & 1023;

    const int rowL = tid >> 3;
    const int c16 = tid & 7;

    float acc[4][4][4];
#pragma unroll
    for (int i = 0; i < 4; i++)
#pragma unroll
        for (int j = 0; j < 4; j++)
#pragma unroll
            for (int r = 0; r < 4; r++) acc[i][j][r] = 0.f;

    const int aRow = warpM * 64 + (lane & 15);
    const int aHalf = (lane >> 4) * 16;
    const int bRow = warpN * 32 + (lane & 7);
    const int bHalf = ((lane >> 3) & 1) * 16;

    int soff[4];
#pragma unroll
    for (int i = 0; i < 4; i++)
        soff[i] = SWZ128((rowL + i * 32) * 128 + c16 * 16);
    const __nv_bfloat16* aSrc = A2 + (size_t)(bi + rowL) * K3 + c16 * 8;
    const __nv_bfloat16* bSrc = B2 + (size_t)(gcol + rowL) * K3 + c16 * 8;

#define GEMM_ISSUE(c, s) do {                                                  \
    const int _k0 = (c) * 64;                                                  \
    const uint32_t _da = s0 + (s) * 16384;                                     \
    const uint32_t _db = s0 + 32768 + (s) * 16384;                             \
    _Pragma("unroll")                                                          \
    for (int _i = 0; _i < 4; _i++) {                                           \
        cp_async16(_da + soff[_i], aSrc + (size_t)_i * 32 * K3 + _k0);         \
        cp_async16(_db + soff[_i], bSrc + (size_t)_i * 32 * K3 + _k0);         \
    }                                                                          \
    cp_commit();                                                               \
} while (0)

    GEMM_ISSUE(0, 0);
    GEMM_ISSUE(1, 1);

    for (int c = 0; c < GEMM_NCHUNK; c++) {
        if (c + 1 < GEMM_NCHUNK)
            asm volatile("cp.async.wait_group 1;" ::: "memory");
        else
            asm volatile("cp.async.wait_group 0;" ::: "memory");
        __syncthreads();
        const int s = c & 1;
        const uint32_t sa = s0 + s * 16384;
        const uint32_t sb = s0 + 32768 + s * 16384;
#pragma unroll
        for (int st = 0; st < 4; st++) {
            uint32_t af[4][4], bf[4][2];
#pragma unroll
            for (int i = 0; i < 4; i++)
                ldm_x4(af[i], sa + SWZ128((aRow + i * 16) * 128 + st * 32 + aHalf));
#pragma unroll
            for (int j = 0; j < 4; j++)
                ldm_x2(bf[j], sb + SWZ128((bRow + j * 8) * 128 + st * 32 + bHalf));
#pragma unroll
            for (int i = 0; i < 4; i++)
#pragma unroll
                for (int j = 0; j < 4; j++)
                    mma16816(acc[i][j], af[i], bf[j]);
        }
        __syncthreads();
        if (c + 2 < GEMM_NCHUNK) GEMM_ISSUE(c + 2, s);
    }
#undef GEMM_ISSUE

#pragma unroll
    for (int i = 0; i < 4; i++) {
        const int r0 = bi + warpM * 64 + i * 16 + (lane >> 2);
#pragma unroll
        for (int j = 0; j < 4; j++) {
            const int c0 = bj + warpN * 32 + j * 8 + (lane & 3) * 2;
            const float b0 = bias[c0], b1 = bias[c0 + 1];
            float2 o0 = make_float2(acc[i][j][0] + b0, acc[i][j][1] + b1);
            float2 o1 = make_float2(acc[i][j][2] + b0, acc[i][j][3] + b1);
            *(float2*)(C + (size_t)r0 * DD + c0) = o0;
            *(float2*)(C + (size_t)(r0 + 8) * DD + c0) = o1;
        }
    }
}

// ---------------------------------------------------------------------------
// Fused norm+split for q/k/v in one launch: grid (NROWS, 3).
// y=0: q (norm+writeback), y=1: k (norm), y=2: v (no norm).
// ---------------------------------------------------------------------------
__global__ __launch_bounds__(256) void norm_split_kernel(
    float* __restrict__ q, float* __restrict__ k, float* __restrict__ v,
    __nv_bfloat16* __restrict__ qs, __nv_bfloat16* __restrict__ ks,
    __nv_bfloat16* __restrict__ vs) {
    const int task = blockIdx.y;
    float* p = (task == 0) ? q : (task == 1) ? k : v;
    __nv_bfloat16* Y = (task == 0) ? qs : (task == 1) ? ks : vs;
    const int do_norm = (task < 2), writeback = (task == 0);

    const int row = blockIdx.x;
    const int b = row >> 11, t = row & 2047;
    const int tid = threadIdx.x;
    __shared__ float red[8];
    float4 a = *(const float4*)(p + (size_t)row * DD + tid * 4);
    if (do_norm) {
        float ss = a.x * a.x + a.y * a.y + a.z * a.z + a.w * a.w;
#pragma unroll
        for (int m = 16; m; m >>= 1) ss += __shfl_xor_sync(0xffffffffu, ss, m);
        if ((tid & 31) == 0) red[tid >> 5] = ss;
        __syncthreads();
        float tot = red[0] + red[1] + red[2] + red[3] +
                    red[4] + red[5] + red[6] + red[7];
        float inv = 1.0f / fmaxf(sqrtf(tot), 1e-12f);
        a.x *= inv; a.y *= inv; a.z *= inv; a.w *= inv;
        if (writeback)
            *(float4*)(p + (size_t)row * DD + tid * 4) = a;
    }
    const int h = tid >> 4;
    const int dh = (tid & 15) * 4;
    __nv_bfloat16* dst = Y + ((size_t)(b * HH + h) * TT + t) * 64 + dh;
    __nv_bfloat16 hi[4], lo[4];
    const float* av = (const float*)&a;
#pragma unroll
    for (int i = 0; i < 4; i++) {
        hi[i] = __float2bfloat16(av[i]);
        lo[i] = __float2bfloat16(av[i] - __bfloat162float(hi[i]));
    }
    *(uint2*)dst = *(const uint2*)hi;
    *(uint2*)(dst + PLANE) = *(const uint2*)lo;
}

// ---------------------------------------------------------------------------
// Flash attention via bf16 mma, hi/lo 3-term splits.
// Q fragments hoisted to registers; K/V cp.async double-buffered (2x32KB).
// smem: stage s at s*32768: Kh +0, Kl +8192, Vh +16384, Vl +24576.
// ---------------------------------------------------------------------------
#define FLM_SMEM 65536

__global__ __launch_bounds__(256, 2) void flash_mma_kernel(
    const __nv_bfloat16* __restrict__ qs, const __nv_bfloat16* __restrict__ ks,
    const __nv_bfloat16* __restrict__ vs, float* __restrict__ attn) {
    extern __shared__ char sm[];
    const uint32_t s0 = smem_u32(sm);

    const int qt = 15 - blockIdx.x;
    const int h = blockIdx.y, b = blockIdx.z;
    const int tid = threadIdx.x, wid = tid >> 5, lane = tid & 31;
    const size_t hb = ((size_t)(b * HH + h)) * TT * 64;

    // ---- prologue: load Q tile to smem, hoist fragments to registers ----
    {
        const int row = tid >> 1, part = tid & 1;
        const __nv_bfloat16* srcH = qs + hb + (size_t)(qt * 128 + row) * 64 + part * 32;
        const __nv_bfloat16* srcL = srcH + PLANE;
#pragma unroll
        for (int i = 0; i < 4; i++) {
            const int off = SWZ128(row * 128 + part * 64 + i * 16);
            *(uint4*)(sm + off) = *(const uint4*)(srcH + i * 8);
            *(uint4*)(sm + 16384 + off) = *(const uint4*)(srcL + i * 8);
        }
    }
    __syncthreads();
    uint32_t qh[4][4], ql[4][4];
    {
        const int qRow = wid * 16 + (lane & 15);
        const int qHalf = (lane >> 4) * 16;
#pragma unroll
        for (int s4 = 0; s4 < 4; s4++) {
            ldm_x4(qh[s4], s0 + SWZ128(qRow * 128 + s4 * 32 + qHalf));
            ldm_x4(ql[s4], s0 + 16384 + SWZ128(qRow * 128 + s4 * 32 + qHalf));
        }
    }
    __syncthreads();   // Q smem now reusable as K/V stage 0

    float out[8][4];
#pragma unroll
    for (int nt = 0; nt < 8; nt++)
#pragma unroll
        for (int r = 0; r < 4; r++) out[nt][r] = 0.f;
    float m0 = -1e30f, m1 = -1e30f, l0 = 0.f, l1 = 0.f;

    const int r4 = lane >> 2;
    const int cpair = (lane & 3) * 2;
    const int rowg0 = qt * 128 + wid * 16 + r4;
    const int rowg1 = rowg0 + 8;
    const int rowmax = qt * 128 + wid * 16 + 15;
    const int warpmin = qt * 128 + wid * 16;

    const int kRowL = lane & 7;
    const int kHalf = ((lane >> 3) & 1) * 16;
    const int vRowL = (lane & 7) + ((lane >> 3) & 1) * 8;

    // per-thread K/V cp.async slice
    const int ldRow = tid >> 2, ldC = tid & 3;
    const int d0 = SWZ128(ldRow * 128 + ldC * 32);
    const int d1 = SWZ128(ldRow * 128 + ldC * 32 + 16);
    const size_t srcOff0 = (size_t)ldRow * 64 + ldC * 16;

#define FL_ISSUE(kt_, s_) do {                                                 \
    const size_t _src = hb + (size_t)(kt_) * 64 * 64 + srcOff0;                \
    const uint32_t _b = s0 + (s_) * 32768;                                     \
    cp_async16(_b + d0,         ks + _src);                                    \
    cp_async16(_b + d1,         ks + _src + 8);                                \
    cp_async16(_b + 8192 + d0,  ks + PLANE + _src);                            \
    cp_async16(_b + 8192 + d1,  ks + PLANE + _src + 8);                        \
    cp_async16(_b + 16384 + d0, vs + _src);                                    \
    cp_async16(_b + 16384 + d1, vs + _src + 8);                                \
    cp_async16(_b + 24576 + d0, vs + PLANE + _src);                            \
    cp_async16(_b + 24576 + d1, vs + PLANE + _src + 8);                        \
    cp_commit();                                                               \
} while (0)

    const int ktmax = 2 * qt + 1;
    FL_ISSUE(0, 0);
    FL_ISSUE(1, 1);

    for (int kt = 0; kt <= ktmax; kt++) {
        const int j0 = kt * 64;
        if (kt < ktmax)
            asm volatile("cp.async.wait_group 1;" ::: "memory");
        else
            asm volatile("cp.async.wait_group 0;" ::: "memory");
        __syncthreads();
        const int s = kt & 1;
        const uint32_t sKh = s0 + s * 32768;
        const uint32_t sKl = sKh + 8192;
        const uint32_t sVh = sKh + 16384;
        const uint32_t sVl = sKh + 24576;

        if (j0 <= rowmax) {
            // ---- S = Q K^T (3-term split) ----
            float sc[8][4];
#pragma unroll
            for (int nt = 0; nt < 8; nt++)
#pragma unroll
                for (int r = 0; r < 4; r++) sc[nt][r] = 0.f;
#pragma unroll
            for (int s4 = 0; s4 < 4; s4++) {
#pragma unroll
                for (int nt = 0; nt < 8; nt++) {
                    uint32_t bh[2], bl[2];
                    const int boff = SWZ128((nt * 8 + kRowL) * 128 + s4 * 32 + kHalf);
                    ldm_x2(bh, sKh + boff);
                    ldm_x2(bl, sKl + boff);
                    mma16816(sc[nt], qh[s4], bh);
                    mma16816(sc[nt], ql[s4], bh);
                    mma16816(sc[nt], qh[s4], bl);
                }
            }

            // ---- scale + causal mask ----
            if (j0 + 63 > warpmin) {
#pragma unroll
                for (int nt = 0; nt < 8; nt++) {
                    const int c0 = j0 + nt * 8 + cpair;
                    sc[nt][0] = (c0     > rowg0) ? -1e30f : sc[nt][0] * SCALE_F;
                    sc[nt][1] = (c0 + 1 > rowg0) ? -1e30f : sc[nt][1] * SCALE_F;
                    sc[nt][2] = (c0     > rowg1) ? -1e30f : sc[nt][2] * SCALE_F;
                    sc[nt][3] = (c0 + 1 > rowg1) ? -1e30f : sc[nt][3] * SCALE_F;
                }
            } else {
#pragma unroll
                for (int nt = 0; nt < 8; nt++)
#pragma unroll
                    for (int r = 0; r < 4; r++) sc[nt][r] *= SCALE_F;
            }

            // ---- online softmax ----
            float ml0 = -1e30f, ml1 = -1e30f;
#pragma unroll
            for (int nt = 0; nt < 8; nt++) {
                ml0 = fmaxf(ml0, fmaxf(sc[nt][0], sc[nt][1]));
                ml1 = fmaxf(ml1, fmaxf(sc[nt][2], sc[nt][3]));
            }
            ml0 = fmaxf(ml0, __shfl_xor_sync(0xffffffffu, ml0, 1));
            ml0 = fmaxf(ml0, __shfl_xor_sync(0xffffffffu, ml0, 2));
            ml1 = fmaxf(ml1, __shfl_xor_sync(0xffffffffu, ml1, 1));
            ml1 = fmaxf(ml1, __shfl_xor_sync(0xffffffffu, ml1, 2));
            const float mn0 = fmaxf(m0, ml0), mn1 = fmaxf(m1, ml1);
            const float a0 = __expf(m0 - mn0), a1 = __expf(m1 - mn1);
            m0 = mn0; m1 = mn1;
            float ps0 = 0.f, ps1 = 0.f;
#pragma unroll
            for (int nt = 0; nt < 8; nt++) {
                sc[nt][0] = __expf(sc[nt][0] - mn0); ps0 += sc[nt][0];
                sc[nt][1] = __expf(sc[nt][1] - mn0); ps0 += sc[nt][1];
                sc[nt][2] = __expf(sc[nt][2] - mn1); ps1 += sc[nt][2];
                sc[nt][3] = __expf(sc[nt][3] - mn1); ps1 += sc[nt][3];
            }
            ps0 += __shfl_xor_sync(0xffffffffu, ps0, 1);
            ps0 += __shfl_xor_sync(0xffffffffu, ps0, 2);
            ps1 += __shfl_xor_sync(0xffffffffu, ps1, 1);
            ps1 += __shfl_xor_sync(0xffffffffu, ps1, 2);
            l0 = l0 * a0 + ps0;
            l1 = l1 * a1 + ps1;
#pragma unroll
            for (int nt = 0; nt < 8; nt++) {
                out[nt][0] *= a0; out[nt][1] *= a0;
                out[nt][2] *= a1; out[nt][3] *= a1;
            }

            // ---- O += P V (3-term split) ----
#pragma unroll
            for (int s4 = 0; s4 < 4; s4++) {
                uint32_t ph[4], pl[4];
                {
                    const float p00 = sc[2 * s4][0],     p01 = sc[2 * s4][1];
                    const float p02 = sc[2 * s4][2],     p03 = sc[2 * s4][3];
                    const float p10 = sc[2 * s4 + 1][0], p11 = sc[2 * s4 + 1][1];
                    const float p12 = sc[2 * s4 + 1][2], p13 = sc[2 * s4 + 1][3];
                    ph[0] = packbf2(p00, p01);
                    ph[1] = packbf2(p02, p03);
                    ph[2] = packbf2(p10, p11);
                    ph[3] = packbf2(p12, p13);
                    pl[0] = packbf2(p00 - __bfloat162float(__float2bfloat16(p00)),
                                    p01 - __bfloat162float(__float2bfloat16(p01)));
                    pl[1] = packbf2(p02 - __bfloat162float(__float2bfloat16(p02)),
                                    p03 - __bfloat162float(__float2bfloat16(p03)));
                    pl[2] = packbf2(p10 - __bfloat162float(__float2bfloat16(p10)),
                                    p11 - __bfloat162float(__float2bfloat16(p11)));
                    pl[3] = packbf2(p12 - __bfloat162float(__float2bfloat16(p12)),
                                    p13 - __bfloat162float(__float2bfloat16(p13)));
                }
#pragma unroll
                for (int nt = 0; nt < 8; nt++) {
                    uint32_t vh[2], vl[2];
                    const int voff = SWZ128((16 * s4 + vRowL) * 128 + nt * 16);
                    ldm_x2t(vh, sVh + voff);
                    ldm_x2t(vl, sVl + voff);
                    mma16816(out[nt], ph, vh);
                    mma16816(out[nt], ph, vl);
                    mma16816(out[nt], pl, vh);
                }
            }
        }
        __syncthreads();
        if (kt + 2 <= ktmax) FL_ISSUE(kt + 2, s);
    }
#undef FL_ISSUE

    const float inv0 = 1.0f / l0, inv1 = 1.0f / l1;
#pragma unroll
    for (int nt = 0; nt < 8; nt++) {
        const int col = h * 64 + nt * 8 + cpair;
        *(float2*)(attn + ((size_t)b * TT + rowg0) * DD + col) =
            make_float2(out[nt][0] * inv0, out[nt][1] * inv0);
        *(float2*)(attn + ((size_t)b * TT + rowg1) * DD + col) =
            make_float2(out[nt][2] * inv1, out[nt][3] * inv1);
    }
}

// ---------------------------------------------------------------------------
// KNN memory attention + gated combine + bf16 round-trip -> split planes.
// ---------------------------------------------------------------------------
__global__ __launch_bounds__(256) void mem_combine_split_kernel(
    const float* __restrict__ q, const float* __restrict__ attn,
    const float* __restrict__ mem_bank, const int* __restrict__ knn_idx,
    const float* __restrict__ gate, __nv_bfloat16* __restrict__ Y) {
    const int bt = blockIdx.x;
    const int b = bt / TT;
    const int tid = threadIdx.x;
    const int h = tid >> 4, s16 = tid & 15;
    const int off = h * HDIM + s16 * 4;

    float4 q4 = *(const float4*)(q + (size_t)bt * DD + off);

    int idxs[KNN];
#pragma unroll
    for (int kk = 0; kk < KNN; kk++) idxs[kk] = knn_idx[bt * KNN + kk];

    float logit[KNN];
#pragma unroll
    for (int kk = 0; kk < KNN; kk++) {
        const float* mk = mem_bank + (((size_t)b * MM + idxs[kk]) * 2 + 0) * DD + off;
        float4 m4 = *(const float4*)mk;
        float d = q4.x * m4.x + q4.y * m4.y + q4.z * m4.z + q4.w * m4.w;
        d += __shfl_xor_sync(0xffffffffu, d, 1);
        d += __shfl_xor_sync(0xffffffffu, d, 2);
        d += __shfl_xor_sync(0xffffffffu, d, 4);
        d += __shfl_xor_sync(0xffffffffu, d, 8);
        logit[kk] = d * SCALE_F;
    }
    float m = fmaxf(logit[0], fmaxf(logit[1], logit[2]));
    float w0 = __expf(logit[0] - m);
    float w1 = __expf(logit[1] - m);
    float w2 = __expf(logit[2] - m);
    const float inv = 1.0f / (w0 + w1 + w2);
    w0 *= inv; w1 *= inv; w2 *= inv;
    const float wk[KNN] = {w0, w1, w2};

    float4 acc = {0.f, 0.f, 0.f, 0.f};
#pragma unroll
    for (int kk = 0; kk < KNN; kk++) {
        const float* mv = mem_bank + (((size_t)b * MM + idxs[kk]) * 2 + 1) * DD + off;
        float4 m4 = *(const float4*)mv;
        acc.x = fmaf(wk[kk], m4.x, acc.x);
        acc.y = fmaf(wk[kk], m4.y, acc.y);
        acc.z = fmaf(wk[kk], m4.z, acc.z);
        acc.w = fmaf(wk[kk], m4.w, acc.w);
    }

    const float g = gate[h];
    const float gi = 1.0f - g;
    float4 a4 = *(const float4*)(attn + (size_t)bt * DD + off);
    float cv[4];
    cv[0] = __bfloat162float(__float2bfloat16(acc.x * g + a4.x * gi));
    cv[1] = __bfloat162float(__float2bfloat16(acc.y * g + a4.y * gi));
    cv[2] = __bfloat162float(__float2bfloat16(acc.z * g + a4.z * gi));
    cv[3] = __bfloat162float(__float2bfloat16(acc.w * g + a4.w * gi));

    __nv_bfloat16 hi[4], lo[4];
#pragma unroll
    for (int i = 0; i < 4; i++) {
        hi[i] = __float2bfloat16(cv[i]);
        lo[i] = __float2bfloat16(cv[i] - __bfloat162float(hi[i]));
    }
    __nv_bfloat16* y = Y + (size_t)bt * K3 + off;
    *(uint2*)y = *(const uint2*)hi;
    *(uint2*)(y + 1024) = *(const uint2*)hi;
    *(uint2*)(y + 2048) = *(const uint2*)lo;
}

// ---------------------------------------------------------------------------
extern "C" void kernel_launch(void* const* d_in, const int* in_sizes, int n_in,
                              void* d_out, int out_size) {
    const float* x    = (const float*)d_in[0];
    const float* Wq   = (const float*)d_in[1];
    const float* bq   = (const float*)d_in[2];
    const float* Wk   = (const float*)d_in[3];
    const float* bk   = (const float*)d_in[4];
    const float* Wv   = (const float*)d_in[5];
    const float* bv   = (const float*)d_in[6];
    const float* Wo   = (const float*)d_in[7];
    const float* bo   = (const float*)d_in[8];
    const float* gate = (const float*)d_in[9];
    const float* memb = (const float*)d_in[10];
    const int*   knn  = (const int*)d_in[11];
    float* out = (float*)d_out;

    float *q, *k, *v, *attn;
    __nv_bfloat16 *x2, *wqkv, *qs, *ks, *vs;
    cudaGetSymbolAddress((void**)&q, g_q);
    cudaGetSymbolAddress((void**)&k, g_k);
    cudaGetSymbolAddress((void**)&v, g_v);
    cudaGetSymbolAddress((void**)&attn, g_attn);
    cudaGetSymbolAddress((void**)&x2, g_x2);
    cudaGetSymbolAddress((void**)&wqkv, g_wqkv);
    cudaGetSymbolAddress((void**)&qs, g_qs);
    cudaGetSymbolAddress((void**)&ks, g_ks);
    cudaGetSymbolAddress((void**)&vs, g_vs);

    cudaFuncSetAttribute(flash_mma_kernel,
                         cudaFuncAttributeMaxDynamicSharedMemorySize, FLM_SMEM);
    cudaFuncSetAttribute(gemm_mma_kernel,
                         cudaFuncAttributeMaxDynamicSharedMemorySize, GEMM_SMEM);

    // one-shot split of x and all four weight matrices
    split_all_kernel<<<32768, 256>>>(x, Wq, Wk, Wv, Wo, x2, wqkv);

    // fused QKV GEMM: grid (24, 32)
    gemm_mma_kernel<<<dim3(24, NROWS / 128), 256, GEMM_SMEM>>>(
        x2, wqkv, bq, bk, bv, q, k, v);

    // fused normalize+split of q/k/v
    norm_split_kernel<<<dim3(NROWS, 3), 256>>>(q, k, v, qs, ks, vs);

    flash_mma_kernel<<<dim3(16, HH, BB), 256, FLM_SMEM>>>(qs, ks, vs, attn);

    // fused KNN combine + split (writes x2 directly)
    mem_combine_split_kernel<<<NROWS, 256>>>(q, attn, memb, knn, gate, x2);

    // O projection (Wo in slot 3 of the split-weight buffer)
    gemm_mma_kernel<<<dim3(8, NROWS / 128), 256, GEMM_SMEM>>>(
        x2, wqkv + (size_t)3 * DD * K3, bo, bo, bo, out, out, out);
}